// round 9
// baseline (speedup 1.0000x reference)
#include <cuda_runtime.h>
#include <math.h>
#include <stdint.h>

#define BB 4
#define TT 2048
#define DD 1024
#define DK 128
#define RR (BB*TT)   // 8192

#define BKV 32
#define CHUNK 8             // KV tiles per flash block
#define BPB 72              // flash blocks per batch: sum_{q=0..15} ceil((q+1)/2)
#define NSLOT (BB*BPB)      // 288 partial slots

// Scratch (device globals: allocation-free)
__device__ float g_Q[RR*DK];
__device__ float g_K[RR*DK];
__device__ float g_V[RR*DK];
__device__ float g_O[RR*DK];
__device__ float g_pO[(size_t)NSLOT*128*DK];   // partial O per chunk slot
__device__ float g_pml[NSLOT*128*2];           // partial (m,l) per row

__device__ __forceinline__ unsigned f2tf(float f) {
    unsigned u; asm("cvt.rna.tf32.f32 %0, %1;" : "=r"(u) : "f"(f)); return u;
}

__device__ __forceinline__ void mma_tf32(float c[4],
    unsigned a0, unsigned a1, unsigned a2, unsigned a3,
    unsigned b0, unsigned b1)
{
    asm volatile(
        "mma.sync.aligned.m16n8k8.row.col.f32.tf32.tf32.f32 "
        "{%0,%1,%2,%3}, {%4,%5,%6,%7}, {%8,%9}, {%0,%1,%2,%3};"
        : "+f"(c[0]), "+f"(c[1]), "+f"(c[2]), "+f"(c[3])
        : "r"(a0), "r"(a1), "r"(a2), "r"(a3), "r"(b0), "r"(b1));
}

// ---------------------------------------------------------------------------
// tf32 GEMM, double-buffered + register-prefetch pipeline (R7, passing).
// C[128x128 tile] = A[M,K] @ B[K,N], row-major fp32 in/out.
// 256 threads = 8 warps as 2(m) x 4(n); warp tile 64x32; BK=32.
// ---------------------------------------------------------------------------
#define GST 136

__device__ __forceinline__ void gemm128_tf32(
    const float* __restrict__ A, const float* __restrict__ Bw,
    float* __restrict__ C, int N, int K, int m0, int n0)
{
    __shared__ unsigned As[2 * 32 * GST];
    __shared__ unsigned Bs[2 * 32 * GST];

    const int tid = threadIdx.x, lane = tid & 31, w = tid >> 5;
    const int wm = (w >> 2) * 64, wn = (w & 3) * 32;
    const int g = lane >> 2, c = lane & 3;

    float acc[4][4][4];
#pragma unroll
    for (int mf = 0; mf < 4; mf++)
#pragma unroll
        for (int nf = 0; nf < 4; nf++)
#pragma unroll
            for (int j = 0; j < 4; j++) acc[mf][nf][j] = 0.f;

    const int arow = tid >> 1, acol = (tid & 1) * 16;   // A: 128 rows x 32 k
    const int brow = tid >> 3, bcol = (tid & 7) * 4;    // B: 32 k x 128 n

    float4 av[4], bv[4];
#pragma unroll
    for (int i = 0; i < 4; i++) {
        av[i] = *(const float4*)&A[(size_t)(m0 + arow) * K + acol + i * 4];
        bv[i] = *(const float4*)&Bw[(size_t)brow * N + n0 + bcol + i * 32];
    }

    int s = 0;
    for (int k0 = 0; k0 < K; k0 += 32) {
        unsigned* Ab = As + s * 32 * GST;
        unsigned* Bb = Bs + s * 32 * GST;
#pragma unroll
        for (int i = 0; i < 4; i++) {
            int kk = acol + i * 4;
            Ab[(kk + 0) * GST + arow] = f2tf(av[i].x);
            Ab[(kk + 1) * GST + arow] = f2tf(av[i].y);
            Ab[(kk + 2) * GST + arow] = f2tf(av[i].z);
            Ab[(kk + 3) * GST + arow] = f2tf(av[i].w);
            uint4 u = {f2tf(bv[i].x), f2tf(bv[i].y), f2tf(bv[i].z), f2tf(bv[i].w)};
            *(uint4*)&Bb[brow * GST + bcol + i * 32] = u;
        }
        __syncthreads();

        if (k0 + 32 < K) {
#pragma unroll
            for (int i = 0; i < 4; i++) {
                av[i] = *(const float4*)&A[(size_t)(m0 + arow) * K + k0 + 32 + acol + i * 4];
                bv[i] = *(const float4*)&Bw[(size_t)(k0 + 32 + brow) * N + n0 + bcol + i * 32];
            }
        }

#pragma unroll
        for (int ks = 0; ks < 4; ks++) {
            const int kk = ks * 8 + c;
            unsigned a[4][4], b[4][2];
#pragma unroll
            for (int mf = 0; mf < 4; mf++) {
                int r = wm + mf * 16 + g;
                a[mf][0] = Ab[kk * GST + r];
                a[mf][1] = Ab[kk * GST + r + 8];
                a[mf][2] = Ab[(kk + 4) * GST + r];
                a[mf][3] = Ab[(kk + 4) * GST + r + 8];
            }
#pragma unroll
            for (int nf = 0; nf < 4; nf++) {
                int n = wn + nf * 8 + g;
                b[nf][0] = Bb[kk * GST + n];
                b[nf][1] = Bb[(kk + 4) * GST + n];
            }
#pragma unroll
            for (int mf = 0; mf < 4; mf++)
#pragma unroll
                for (int nf = 0; nf < 4; nf++)
                    mma_tf32(acc[mf][nf], a[mf][0], a[mf][1], a[mf][2], a[mf][3],
                             b[nf][0], b[nf][1]);
        }
        s ^= 1;
    }

#pragma unroll
    for (int mf = 0; mf < 4; mf++)
#pragma unroll
        for (int nf = 0; nf < 4; nf++) {
            size_t r0 = (size_t)(m0 + wm + mf * 16 + g) * N + n0 + wn + nf * 8 + 2 * c;
            float2 lo = {acc[mf][nf][0], acc[mf][nf][1]};
            float2 hi = {acc[mf][nf][2], acc[mf][nf][3]};
            *(float2*)&C[r0]                 = lo;
            *(float2*)&C[r0 + (size_t)8 * N] = hi;
        }
}

__global__ __launch_bounds__(256) void qkv_kernel(
    const float* __restrict__ x, const float* __restrict__ Wq,
    const float* __restrict__ Wk, const float* __restrict__ Wv)
{
    const float* W; float* C;
    if (blockIdx.z == 0)      { W = Wq; C = g_Q; }
    else if (blockIdx.z == 1) { W = Wk; C = g_K; }
    else                      { W = Wv; C = g_V; }
    gemm128_tf32(x, W, C, DK, DD, blockIdx.x * 128, 0);
}

__global__ __launch_bounds__(256) void outproj_kernel(
    const float* __restrict__ Wo, float* __restrict__ out)
{
    gemm128_tf32(g_O, Wo, out, DD, DK, blockIdx.y * 128, blockIdx.x * 128);
}

// ---------------------------------------------------------------------------
// Flash attention, tf32 mma.sync, split-KV.
// BQ=128, BKV=32, 256 threads = 8 warps; warp owns 16 q-rows.
// Chunk = up to 8 KV tiles -> 288 blocks total (one wave at 2 blocks/SM).
// smem: Q (128x132) + single-buffered K (32x132) + V (32x128) = 98.5 KB
// => 2 blocks/SM. P fragments for the PV MMA are built via intra-quad
// shuffles of the exp() values (no Ps smem buffer).
// ---------------------------------------------------------------------------
#define QSS 132
#define KSS 132
#define VSS 128
#define OFF_K (128*QSS)
#define OFF_V (OFF_K + BKV*KSS)
#define FLASH_SMEM ((OFF_V + BKV*VSS) * 4)   // 100,864 bytes

__global__ __launch_bounds__(256, 2) void flash_kernel()
{
    extern __shared__ unsigned smf[];
    unsigned* Qs = smf;
    unsigned* Kb = smf + OFF_K;
    unsigned* Vb = smf + OFF_V;

    const int tid = threadIdx.x, lane = tid & 31, w = tid >> 5;
    const int g = lane >> 2, c = lane & 3;
    const int wm = w * 16;

    // ---- schedule decode: reversed order puts big (qt) chunks first ----
    const int b  = blockIdx.x / BPB;
    const int wr = BPB - 1 - (blockIdx.x % BPB);
    int qt = 0, chunk = 0, prefix = 0;
    {
        int accn = 0;
        for (int q = 0; q < 16; q++) {
            int n = (q + 2) >> 1;          // ceil((4q+4)/8) chunks for q-tile q
            if (wr < accn + n) { qt = q; chunk = wr - accn; prefix = accn; break; }
            accn += n;
        }
    }
    const int slot = b * BPB + prefix + chunk;
    const int q0 = qt * 128;
    const int it_total = 4 * qt + 4;       // BKV=32 tiles for this q-tile
    const int t0 = chunk * CHUNK;
    const int tlen = (it_total - t0 < CHUNK) ? (it_total - t0) : CHUNK;

    const float* Qg = g_Q + ((size_t)b * TT + q0) * DK;
    const float* Kg = g_K + (size_t)b * TT * DK;
    const float* Vg = g_V + (size_t)b * TT * DK;

    // load Q tile (tf32) — covered by the first in-loop barrier
#pragma unroll
    for (int i = 0; i < 16; i++) {
        int idx = i * 256 + tid, r = idx >> 5, c4 = idx & 31;
        float4 v = *(const float4*)&Qg[r * 128 + c4 * 4];
        uint4 u = {f2tf(v.x), f2tf(v.y), f2tf(v.z), f2tf(v.w)};
        *(uint4*)&Qs[r * QSS + c4 * 4] = u;
    }

    float mr0 = -1e30f, mr1 = -1e30f, l0 = 0.f, l1 = 0.f;
    float O[16][4];
#pragma unroll
    for (int nf = 0; nf < 16; nf++)
#pragma unroll
        for (int j = 0; j < 4; j++) O[nf][j] = 0.f;

    const float scale = 0.08838834764831845f;   // 1/sqrt(128)
    const int srcA = (lane & 28) | (c >> 1);    // P-fragment producer lane

    for (int ti = 0; ti < tlen; ti++) {
        const int t = t0 + ti;

        // stage K (tf32, stride 132) and V (tf32, stride 128)
        const float* Kj = Kg + (size_t)t * BKV * DK;
        const float* Vj = Vg + (size_t)t * BKV * DK;
#pragma unroll
        for (int i = 0; i < 4; i++) {
            int idx = i * 256 + tid, r = idx >> 5, c4 = idx & 31;
            float4 kv = *(const float4*)&Kj[r * 128 + c4 * 4];
            uint4 uk = {f2tf(kv.x), f2tf(kv.y), f2tf(kv.z), f2tf(kv.w)};
            *(uint4*)&Kb[r * KSS + c4 * 4] = uk;
            float4 vv = *(const float4*)&Vj[r * 128 + c4 * 4];
            uint4 uv = {f2tf(vv.x), f2tf(vv.y), f2tf(vv.z), f2tf(vv.w)};
            *(uint4*)&Vb[r * VSS + c4 * 4] = uv;
        }
        __syncthreads();

        // --- S = Q K^T : warp 16x32, 4 n-frags ---
        float sfr[4][4];
#pragma unroll
        for (int nf = 0; nf < 4; nf++)
#pragma unroll
            for (int j = 0; j < 4; j++) sfr[nf][j] = 0.f;

#pragma unroll
        for (int ks = 0; ks < 16; ks++) {
            const int kk = ks * 8 + c;
            unsigned a0 = Qs[(wm + g) * QSS + kk];
            unsigned a1 = Qs[(wm + g + 8) * QSS + kk];
            unsigned a2 = Qs[(wm + g) * QSS + kk + 4];
            unsigned a3 = Qs[(wm + g + 8) * QSS + kk + 4];
#pragma unroll
            for (int nf = 0; nf < 4; nf++) {
                int n = nf * 8 + g;
                mma_tf32(sfr[nf], a0, a1, a2, a3,
                         Kb[n * KSS + kk], Kb[n * KSS + kk + 4]);
            }
        }

        // scale + causal mask
#pragma unroll
        for (int nf = 0; nf < 4; nf++)
#pragma unroll
            for (int j = 0; j < 4; j++) sfr[nf][j] *= scale;

        if (t * BKV + BKV - 1 > q0 + wm) {
            const int r0g = q0 + wm + g, r1g = r0g + 8;
#pragma unroll
            for (int nf = 0; nf < 4; nf++) {
                int col = t * BKV + nf * 8 + 2 * c;
                if (col     > r0g) sfr[nf][0] = -1e30f;
                if (col + 1 > r0g) sfr[nf][1] = -1e30f;
                if (col     > r1g) sfr[nf][2] = -1e30f;
                if (col + 1 > r1g) sfr[nf][3] = -1e30f;
            }
        }

        // --- online softmax (rows wm+g, wm+g+8; reduce over 4-lane quad) ---
        float rm0 = -1e30f, rm1 = -1e30f;
#pragma unroll
        for (int nf = 0; nf < 4; nf++) {
            rm0 = fmaxf(rm0, fmaxf(sfr[nf][0], sfr[nf][1]));
            rm1 = fmaxf(rm1, fmaxf(sfr[nf][2], sfr[nf][3]));
        }
        rm0 = fmaxf(rm0, __shfl_xor_sync(0xffffffffu, rm0, 1));
        rm0 = fmaxf(rm0, __shfl_xor_sync(0xffffffffu, rm0, 2));
        rm1 = fmaxf(rm1, __shfl_xor_sync(0xffffffffu, rm1, 1));
        rm1 = fmaxf(rm1, __shfl_xor_sync(0xffffffffu, rm1, 2));

        float mn0 = fmaxf(mr0, rm0), mn1 = fmaxf(mr1, rm1);
        float al0 = __expf(mr0 - mn0), al1 = __expf(mr1 - mn1);
        float sum0 = 0.f, sum1 = 0.f;
#pragma unroll
        for (int nf = 0; nf < 4; nf++) {
            sfr[nf][0] = __expf(sfr[nf][0] - mn0);
            sfr[nf][1] = __expf(sfr[nf][1] - mn0);
            sfr[nf][2] = __expf(sfr[nf][2] - mn1);
            sfr[nf][3] = __expf(sfr[nf][3] - mn1);
            sum0 += sfr[nf][0] + sfr[nf][1];
            sum1 += sfr[nf][2] + sfr[nf][3];
        }
        sum0 += __shfl_xor_sync(0xffffffffu, sum0, 1);
        sum0 += __shfl_xor_sync(0xffffffffu, sum0, 2);
        sum1 += __shfl_xor_sync(0xffffffffu, sum1, 1);
        sum1 += __shfl_xor_sync(0xffffffffu, sum1, 2);

        l0 = l0 * al0 + sum0; l1 = l1 * al1 + sum1;
        mr0 = mn0; mr1 = mn1;
#pragma unroll
        for (int nf = 0; nf < 16; nf++) {
            O[nf][0] *= al0; O[nf][1] *= al0;
            O[nf][2] *= al1; O[nf][3] *= al1;
        }

        // --- O += P V : P a-frags via intra-quad shuffles (no smem P) ---
        const bool odd = (c & 1) != 0;
#pragma unroll
        for (int ks = 0; ks < 4; ks++) {
            float qv0 = __shfl_sync(0xffffffffu, sfr[ks][0], srcA);
            float qv1 = __shfl_sync(0xffffffffu, sfr[ks][1], srcA);
            float qv2 = __shfl_sync(0xffffffffu, sfr[ks][2], srcA);
            float qv3 = __shfl_sync(0xffffffffu, sfr[ks][3], srcA);
            float wv0 = __shfl_sync(0xffffffffu, sfr[ks][0], srcA + 2);
            float wv1 = __shfl_sync(0xffffffffu, sfr[ks][1], srcA + 2);
            float wv2 = __shfl_sync(0xffffffffu, sfr[ks][2], srcA + 2);
            float wv3 = __shfl_sync(0xffffffffu, sfr[ks][3], srcA + 2);
            unsigned a0 = f2tf(odd ? qv1 : qv0);
            unsigned a1 = f2tf(odd ? qv3 : qv2);
            unsigned a2 = f2tf(odd ? wv1 : wv0);
            unsigned a3 = f2tf(odd ? wv3 : wv2);
            const int kk = ks * 8 + c;
#pragma unroll
            for (int nf = 0; nf < 16; nf++) {
                int n = nf * 8 + g;
                mma_tf32(O[nf], a0, a1, a2, a3,
                         Vb[kk * VSS + n], Vb[(kk + 4) * VSS + n]);
            }
        }
        __syncthreads();   // protect K/V smem before next stage
    }

    // ---- write partial (unnormalized O, m, l) ----
    float* pO = g_pO + (size_t)slot * 128 * DK;
#pragma unroll
    for (int nf = 0; nf < 16; nf++) {
        int col = nf * 8 + 2 * c;
        float2 lo = {O[nf][0], O[nf][1]};
        float2 hi = {O[nf][2], O[nf][3]};
        *(float2*)&pO[(wm + g) * DK + col]     = lo;
        *(float2*)&pO[(wm + g + 8) * DK + col] = hi;
    }
    if (c == 0) {
        float* ml = g_pml + slot * 256;
        ml[(wm + g) * 2]         = mr0;
        ml[(wm + g) * 2 + 1]     = l0;
        ml[(wm + g + 8) * 2]     = mr1;
        ml[(wm + g + 8) * 2 + 1] = l1;
    }
}

// ---------------------------------------------------------------------------
// Combine partial chunks -> g_O (normalized). Grid 64 = (b,qt), 256 threads.
// ---------------------------------------------------------------------------
__global__ __launch_bounds__(256) void combine_kernel()
{
    const int b = blockIdx.x >> 4, qt = blockIdx.x & 15;
    const int nch = (qt + 2) >> 1;         // ceil((4qt+4)/8)
    int prefix = 0;
    for (int q = 0; q < qt; q++) prefix += (q + 2) >> 1;
    const int base = b * BPB + prefix;

    const int row = threadIdx.x >> 1;
    const int ch0 = (threadIdx.x & 1) * 64;

    float mv[8], lv[8], wgt[8];
    float M = -1e30f;
    for (int i = 0; i < nch; i++) {
        mv[i] = g_pml[(base + i) * 256 + row * 2];
        lv[i] = g_pml[(base + i) * 256 + row * 2 + 1];
        M = fmaxf(M, mv[i]);
    }
    float L = 0.f;
    for (int i = 0; i < nch; i++) { wgt[i] = __expf(mv[i] - M); L += wgt[i] * lv[i]; }
    const float invL = 1.f / L;

    const size_t orow = ((size_t)b * TT + qt * 128 + row) * DK;
#pragma unroll 4
    for (int j = 0; j < 64; j += 4) {
        float4 a = {0.f, 0.f, 0.f, 0.f};
        for (int i = 0; i < nch; i++) {
            float4 v = *(const float4*)&g_pO[((size_t)(base + i) * 128 + row) * DK + ch0 + j];
            a.x += wgt[i] * v.x; a.y += wgt[i] * v.y;
            a.z += wgt[i] * v.z; a.w += wgt[i] * v.w;
        }
        a.x *= invL; a.y *= invL; a.z *= invL; a.w *= invL;
        *(float4*)&g_O[orow + ch0 + j] = a;
    }
}

// ---------------------------------------------------------------------------
extern "C" void kernel_launch(void* const* d_in, const int* in_sizes, int n_in,
                              void* d_out, int out_size)
{
    const float* x  = (const float*)d_in[0];
    const float* Wq = (const float*)d_in[1];
    const float* Wk = (const float*)d_in[2];
    const float* Wv = (const float*)d_in[3];
    const float* Wo = (const float*)d_in[4];
    float* out = (float*)d_out;

    cudaFuncSetAttribute(flash_kernel,
                         cudaFuncAttributeMaxDynamicSharedMemorySize, FLASH_SMEM);

    // QKV projections (tf32 mma.sync): [8192,1024] @ [1024,128] x3
    qkv_kernel<<<dim3(RR / 128, 1, 3), 256>>>(x, Wq, Wk, Wv);

    // Split-KV causal flash attention (tf32 mma.sync, 2 blocks/SM)
    flash_kernel<<<NSLOT, 256, FLASH_SMEM>>>();

    // Merge partial softmax chunks
    combine_kernel<<<BB * 16, 256>>>();

    // Output projection: [8192,128] @ [128,1024]
    outproj_kernel<<<dim3(DD / 128, RR / 128), 256>>>(Wo, out);
}

// round 10
// speedup vs baseline: 1.2164x; 1.2164x over previous
#include <cuda_runtime.h>
#include <math.h>
#include <stdint.h>

#define BB 4
#define TT 2048
#define DD 1024
#define DK 128
#define RR (BB*TT)   // 8192

#define BKV 32
#define BPB 40              // flash blocks per batch (chunked schedule, chunk=16 tiles)
#define NSLOT (BB*BPB)      // 160 partial slots

// Scratch (device globals: allocation-free)
__device__ float g_Q[RR*DK];
__device__ float g_K[RR*DK];
__device__ float g_V[RR*DK];
__device__ float g_O[RR*DK];
__device__ float g_pO[(size_t)NSLOT*128*DK];   // partial O per chunk slot
__device__ float g_pml[NSLOT*128*2];           // partial (m,l) per row

// pack two f32 -> half2 u32 (lo = first arg, hi = second arg)
__device__ __forceinline__ unsigned f2h2(float lo, float hi) {
    unsigned u;
    asm("cvt.rn.f16x2.f32 %0, %1, %2;" : "=r"(u) : "f"(hi), "f"(lo));
    return u;
}

__device__ __forceinline__ void mma_f16(float c[4],
    unsigned a0, unsigned a1, unsigned a2, unsigned a3,
    unsigned b0, unsigned b1)
{
    asm volatile(
        "mma.sync.aligned.m16n8k16.row.col.f32.f16.f16.f32 "
        "{%0,%1,%2,%3}, {%4,%5,%6,%7}, {%8,%9}, {%0,%1,%2,%3};"
        : "+f"(c[0]), "+f"(c[1]), "+f"(c[2]), "+f"(c[3])
        : "r"(a0), "r"(a1), "r"(a2), "r"(a3), "r"(b0), "r"(b1));
}

// ---------------------------------------------------------------------------
// fp16 GEMM: C[128x128 tile] = A[M,K] @ B[K,N], fp32 in/out, fp32 accum.
// 256 threads = 8 warps as 2(m) x 4(n); warp tile 64x32; BK=32.
// As: [m][k2] packed half2, stride 20 u32 ({4g+c} conflict-free).
// Bs2: [k2][n] packed (pair of k-rows per u32), stride 136 ({8c+g} c-free).
// Double-buffered + register prefetch, one barrier per slab.
// ---------------------------------------------------------------------------
#define AST 20
#define BST 136

__device__ __forceinline__ void gemm128_f16(
    const float* __restrict__ A, const float* __restrict__ Bw,
    float* __restrict__ C, int N, int K, int m0, int n0)
{
    __shared__ unsigned As[2 * 128 * AST];
    __shared__ unsigned Bs[2 * 16 * BST];

    const int tid = threadIdx.x, lane = tid & 31, w = tid >> 5;
    const int wm = (w >> 2) * 64, wn = (w & 3) * 32;
    const int g = lane >> 2, c = lane & 3;

    float acc[4][4][4];
#pragma unroll
    for (int mf = 0; mf < 4; mf++)
#pragma unroll
        for (int nf = 0; nf < 4; nf++)
#pragma unroll
            for (int j = 0; j < 4; j++) acc[mf][nf][j] = 0.f;

    // A staging: thread -> row = tid>>1, 16 floats at k-offset (tid&1)*16
    const int arow = tid >> 1;
    const int aku  = (tid & 1) * 8;       // u32 offset in row (8 u32 = 16 halves)
    // B staging: thread -> k2 = tid>>4 (pair of k rows), n0b = (tid&15)*8
    const int bk2 = tid >> 4;
    const int bn0 = (tid & 15) * 8;

    float4 av[4], bv[4];
#pragma unroll
    for (int i = 0; i < 4; i++)
        av[i] = *(const float4*)&A[(size_t)(m0 + arow) * K + aku * 2 + i * 4];
    bv[0] = *(const float4*)&Bw[(size_t)(2 * bk2)     * N + n0 + bn0];
    bv[1] = *(const float4*)&Bw[(size_t)(2 * bk2)     * N + n0 + bn0 + 4];
    bv[2] = *(const float4*)&Bw[(size_t)(2 * bk2 + 1) * N + n0 + bn0];
    bv[3] = *(const float4*)&Bw[(size_t)(2 * bk2 + 1) * N + n0 + bn0 + 4];

    int s = 0;
    for (int k0 = 0; k0 < K; k0 += 32) {
        unsigned* Ab = As + s * 128 * AST;
        unsigned* Bb = Bs + s * 16 * BST;

        // stage A (row-major packed half2)
        {
            uint4 u0 = {f2h2(av[0].x, av[0].y), f2h2(av[0].z, av[0].w),
                        f2h2(av[1].x, av[1].y), f2h2(av[1].z, av[1].w)};
            uint4 u1 = {f2h2(av[2].x, av[2].y), f2h2(av[2].z, av[2].w),
                        f2h2(av[3].x, av[3].y), f2h2(av[3].z, av[3].w)};
            *(uint4*)&Ab[arow * AST + aku]     = u0;
            *(uint4*)&Ab[arow * AST + aku + 4] = u1;
        }
        // stage B (k-pairs packed)
        {
            uint4 u0 = {f2h2(bv[0].x, bv[2].x), f2h2(bv[0].y, bv[2].y),
                        f2h2(bv[0].z, bv[2].z), f2h2(bv[0].w, bv[2].w)};
            uint4 u1 = {f2h2(bv[1].x, bv[3].x), f2h2(bv[1].y, bv[3].y),
                        f2h2(bv[1].z, bv[3].z), f2h2(bv[1].w, bv[3].w)};
            *(uint4*)&Bb[bk2 * BST + bn0]     = u0;
            *(uint4*)&Bb[bk2 * BST + bn0 + 4] = u1;
        }
        __syncthreads();

        // prefetch next slab (overlaps MMA)
        if (k0 + 32 < K) {
#pragma unroll
            for (int i = 0; i < 4; i++)
                av[i] = *(const float4*)&A[(size_t)(m0 + arow) * K + k0 + 32 + aku * 2 + i * 4];
            bv[0] = *(const float4*)&Bw[(size_t)(k0 + 32 + 2 * bk2)     * N + n0 + bn0];
            bv[1] = *(const float4*)&Bw[(size_t)(k0 + 32 + 2 * bk2)     * N + n0 + bn0 + 4];
            bv[2] = *(const float4*)&Bw[(size_t)(k0 + 32 + 2 * bk2 + 1) * N + n0 + bn0];
            bv[3] = *(const float4*)&Bw[(size_t)(k0 + 32 + 2 * bk2 + 1) * N + n0 + bn0 + 4];
        }

#pragma unroll
        for (int ks = 0; ks < 2; ks++) {
            const int kk = ks * 8 + c;
            unsigned a[4][4], b[4][2];
#pragma unroll
            for (int mf = 0; mf < 4; mf++) {
                int r = wm + mf * 16 + g;
                a[mf][0] = Ab[r * AST + kk];
                a[mf][1] = Ab[(r + 8) * AST + kk];
                a[mf][2] = Ab[r * AST + kk + 4];
                a[mf][3] = Ab[(r + 8) * AST + kk + 4];
            }
#pragma unroll
            for (int nf = 0; nf < 4; nf++) {
                int n = wn + nf * 8 + g;
                b[nf][0] = Bb[kk * BST + n];
                b[nf][1] = Bb[(kk + 4) * BST + n];
            }
#pragma unroll
            for (int mf = 0; mf < 4; mf++)
#pragma unroll
                for (int nf = 0; nf < 4; nf++)
                    mma_f16(acc[mf][nf], a[mf][0], a[mf][1], a[mf][2], a[mf][3],
                            b[nf][0], b[nf][1]);
        }
        s ^= 1;
    }

#pragma unroll
    for (int mf = 0; mf < 4; mf++)
#pragma unroll
        for (int nf = 0; nf < 4; nf++) {
            size_t r0 = (size_t)(m0 + wm + mf * 16 + g) * N + n0 + wn + nf * 8 + 2 * c;
            float2 lo = {acc[mf][nf][0], acc[mf][nf][1]};
            float2 hi = {acc[mf][nf][2], acc[mf][nf][3]};
            *(float2*)&C[r0]                 = lo;
            *(float2*)&C[r0 + (size_t)8 * N] = hi;
        }
}

__global__ __launch_bounds__(256) void qkv_kernel(
    const float* __restrict__ x, const float* __restrict__ Wq,
    const float* __restrict__ Wk, const float* __restrict__ Wv)
{
    const float* W; float* C;
    if (blockIdx.z == 0)      { W = Wq; C = g_Q; }
    else if (blockIdx.z == 1) { W = Wk; C = g_K; }
    else                      { W = Wv; C = g_V; }
    gemm128_f16(x, W, C, DK, DD, blockIdx.x * 128, 0);
}

__global__ __launch_bounds__(256) void outproj_kernel(
    const float* __restrict__ Wo, float* __restrict__ out)
{
    gemm128_f16(g_O, Wo, out, DD, DK, blockIdx.y * 128, blockIdx.x * 128);
}

// ---------------------------------------------------------------------------
// Flash attention, fp16 mma (m16n8k16), split-KV, R6 structure:
// BQ=128, BKV=32, 256 threads = 8 warps (warp owns 16 q-rows), chunk = 16
// tiles, double-buffered K/V, ONE barrier per tile.
// Qs: [m][d2] packed half2, stride 68 u32 (scale folded in).
// Ks: [key][d2] packed, stride 68.  Vs2: [key2][n] key-pair packed, stride 136.
// S fp16 output frags map DIRECTLY to PV A-frags (no P smem, no shuffles).
// smem = 68 KB -> 2 blocks/SM.
// ---------------------------------------------------------------------------
#define QS2 68
#define KS2 68
#define VST 136
#define OFF_K (128*QS2)
#define OFF_V (OFF_K + 2*BKV*KS2)
#define FLASH_SMEM ((OFF_V + 2*16*VST) * 4)   // 69,632 bytes

__global__ __launch_bounds__(256, 2) void flash_kernel()
{
    extern __shared__ unsigned smf[];
    unsigned* Qs = smf;
    unsigned* Ks = smf + OFF_K;
    unsigned* Vs = smf + OFF_V;

    const int tid = threadIdx.x, lane = tid & 31, w = tid >> 5;
    const int g = lane >> 2, c = lane & 3;
    const int wm = w * 16;

    // ---- schedule decode: reversed order puts big (qt) chunks first ----
    const int b  = blockIdx.x / BPB;
    const int wr = BPB - 1 - (blockIdx.x % BPB);
    int qt = 0, chunk = 0, prefix = 0;
    {
        int accn = 0;
        for (int q = 0; q < 16; q++) {
            int n = q / 4 + 1;
            if (wr < accn + n) { qt = q; chunk = wr - accn; prefix = accn; break; }
            accn += n;
        }
    }
    const int slot = b * BPB + prefix + chunk;
    const int q0 = qt * 128;
    const int it_total = 4 * qt + 4;
    const int t0 = chunk * 16;
    const int tlen = (it_total - t0 < 16) ? (it_total - t0) : 16;

    const float* Qg = g_Q + ((size_t)b * TT + q0) * DK;
    const float* Kg = g_K + (size_t)b * TT * DK;
    const float* Vg = g_V + (size_t)b * TT * DK;

    const float scale = 0.08838834764831845f;   // 1/sqrt(128), folded into Q

    // load Q tile (scaled, packed half2). 2 threads per row.
    {
        const int r = tid >> 1, ku = (tid & 1) * 32;
#pragma unroll
        for (int i = 0; i < 8; i++) {
            float4 va = *(const float4*)&Qg[r * 128 + ku * 2 + i * 8];
            float4 vb = *(const float4*)&Qg[r * 128 + ku * 2 + i * 8 + 4];
            uint4 u = {f2h2(va.x * scale, va.y * scale),
                       f2h2(va.z * scale, va.w * scale),
                       f2h2(vb.x * scale, vb.y * scale),
                       f2h2(vb.z * scale, vb.w * scale)};
            *(uint4*)&Qs[r * QS2 + ku + i * 4] = u;
        }
    }

    float mr0 = -1e30f, mr1 = -1e30f, l0 = 0.f, l1 = 0.f;
    float O[16][4];
#pragma unroll
    for (int nf = 0; nf < 16; nf++)
#pragma unroll
        for (int j = 0; j < 4; j++) O[nf][j] = 0.f;

    // staging indices
    const int kr = tid >> 3, kku = (tid & 7) * 8;     // K: row, u32 group
    const int vk2 = tid >> 4, vn0 = (tid & 15) * 8;   // V: key-pair, n group

    int s = 0;
    for (int ti = 0; ti < tlen; ti++) {
        const int t = t0 + ti;
        unsigned* Kb = Ks + s * BKV * KS2;
        unsigned* Vb = Vs + s * 16 * VST;

        // stage K tile (packed half2, row-major)
        {
            const float* Kj = Kg + (size_t)t * BKV * DK;
            float4 v0 = *(const float4*)&Kj[kr * 128 + kku * 2];
            float4 v1 = *(const float4*)&Kj[kr * 128 + kku * 2 + 4];
            float4 v2 = *(const float4*)&Kj[kr * 128 + kku * 2 + 8];
            float4 v3 = *(const float4*)&Kj[kr * 128 + kku * 2 + 12];
            uint4 u0 = {f2h2(v0.x, v0.y), f2h2(v0.z, v0.w),
                        f2h2(v1.x, v1.y), f2h2(v1.z, v1.w)};
            uint4 u1 = {f2h2(v2.x, v2.y), f2h2(v2.z, v2.w),
                        f2h2(v3.x, v3.y), f2h2(v3.z, v3.w)};
            *(uint4*)&Kb[kr * KS2 + kku]     = u0;
            *(uint4*)&Kb[kr * KS2 + kku + 4] = u1;
        }
        // stage V tile (key pairs packed into half2)
        {
            const float* Vj = Vg + (size_t)t * BKV * DK;
            float4 e0 = *(const float4*)&Vj[(2 * vk2)     * 128 + vn0];
            float4 e1 = *(const float4*)&Vj[(2 * vk2)     * 128 + vn0 + 4];
            float4 o0 = *(const float4*)&Vj[(2 * vk2 + 1) * 128 + vn0];
            float4 o1 = *(const float4*)&Vj[(2 * vk2 + 1) * 128 + vn0 + 4];
            uint4 u0 = {f2h2(e0.x, o0.x), f2h2(e0.y, o0.y),
                        f2h2(e0.z, o0.z), f2h2(e0.w, o0.w)};
            uint4 u1 = {f2h2(e1.x, o1.x), f2h2(e1.y, o1.y),
                        f2h2(e1.z, o1.z), f2h2(e1.w, o1.w)};
            *(uint4*)&Vb[vk2 * VST + vn0]     = u0;
            *(uint4*)&Vb[vk2 * VST + vn0 + 4] = u1;
        }
        __syncthreads();

        // --- S = Q K^T : warp 16x32, 4 n-frags, 8 k16-slices ---
        float sfr[4][4];
#pragma unroll
        for (int nf = 0; nf < 4; nf++)
#pragma unroll
            for (int j = 0; j < 4; j++) sfr[nf][j] = 0.f;

#pragma unroll
        for (int ks = 0; ks < 8; ks++) {
            const int kk = ks * 8 + c;
            unsigned a0 = Qs[(wm + g) * QS2 + kk];
            unsigned a1 = Qs[(wm + g + 8) * QS2 + kk];
            unsigned a2 = Qs[(wm + g) * QS2 + kk + 4];
            unsigned a3 = Qs[(wm + g + 8) * QS2 + kk + 4];
#pragma unroll
            for (int nf = 0; nf < 4; nf++) {
                int n = nf * 8 + g;
                mma_f16(sfr[nf], a0, a1, a2, a3,
                        Kb[n * KS2 + kk], Kb[n * KS2 + kk + 4]);
            }
        }

        // causal mask (scale already folded into Q)
        if (t * BKV + BKV - 1 > q0 + wm) {
            const int r0g = q0 + wm + g, r1g = r0g + 8;
#pragma unroll
            for (int nf = 0; nf < 4; nf++) {
                int col = t * BKV + nf * 8 + 2 * c;
                if (col     > r0g) sfr[nf][0] = -1e30f;
                if (col + 1 > r0g) sfr[nf][1] = -1e30f;
                if (col     > r1g) sfr[nf][2] = -1e30f;
                if (col + 1 > r1g) sfr[nf][3] = -1e30f;
            }
        }

        // --- online softmax (rows wm+g, wm+g+8; reduce over 4-lane quad) ---
        float rm0 = -1e30f, rm1 = -1e30f;
#pragma unroll
        for (int nf = 0; nf < 4; nf++) {
            rm0 = fmaxf(rm0, fmaxf(sfr[nf][0], sfr[nf][1]));
            rm1 = fmaxf(rm1, fmaxf(sfr[nf][2], sfr[nf][3]));
        }
        rm0 = fmaxf(rm0, __shfl_xor_sync(0xffffffffu, rm0, 1));
        rm0 = fmaxf(rm0, __shfl_xor_sync(0xffffffffu, rm0, 2));
        rm1 = fmaxf(rm1, __shfl_xor_sync(0xffffffffu, rm1, 1));
        rm1 = fmaxf(rm1, __shfl_xor_sync(0xffffffffu, rm1, 2));

        float mn0 = fmaxf(mr0, rm0), mn1 = fmaxf(mr1, rm1);
        float al0 = __expf(mr0 - mn0), al1 = __expf(mr1 - mn1);
        float sum0 = 0.f, sum1 = 0.f;
#pragma unroll
        for (int nf = 0; nf < 4; nf++) {
            sfr[nf][0] = __expf(sfr[nf][0] - mn0);
            sfr[nf][1] = __expf(sfr[nf][1] - mn0);
            sfr[nf][2] = __expf(sfr[nf][2] - mn1);
            sfr[nf][3] = __expf(sfr[nf][3] - mn1);
            sum0 += sfr[nf][0] + sfr[nf][1];
            sum1 += sfr[nf][2] + sfr[nf][3];
        }
        sum0 += __shfl_xor_sync(0xffffffffu, sum0, 1);
        sum0 += __shfl_xor_sync(0xffffffffu, sum0, 2);
        sum1 += __shfl_xor_sync(0xffffffffu, sum1, 1);
        sum1 += __shfl_xor_sync(0xffffffffu, sum1, 2);

        l0 = l0 * al0 + sum0; l1 = l1 * al1 + sum1;
        mr0 = mn0; mr1 = mn1;
#pragma unroll
        for (int nf = 0; nf < 16; nf++) {
            O[nf][0] *= al0; O[nf][1] *= al0;
            O[nf][2] *= al1; O[nf][3] *= al1;
        }

        // --- O += P V : S-frags pack directly into PV A-frags ---
#pragma unroll
        for (int ksl = 0; ksl < 2; ksl++) {
            unsigned a0 = f2h2(sfr[2 * ksl][0],     sfr[2 * ksl][1]);
            unsigned a1 = f2h2(sfr[2 * ksl][2],     sfr[2 * ksl][3]);
            unsigned a2 = f2h2(sfr[2 * ksl + 1][0], sfr[2 * ksl + 1][1]);
            unsigned a3 = f2h2(sfr[2 * ksl + 1][2], sfr[2 * ksl + 1][3]);
            const int kk = ksl * 8 + c;
#pragma unroll
            for (int nf = 0; nf < 16; nf++) {
                int n = nf * 8 + g;
                mma_f16(O[nf], a0, a1, a2, a3,
                        Vb[kk * VST + n], Vb[(kk + 4) * VST + n]);
            }
        }
        s ^= 1;
    }

    // ---- write partial (unnormalized O, m, l) ----
    float* pO = g_pO + (size_t)slot * 128 * DK;
#pragma unroll
    for (int nf = 0; nf < 16; nf++) {
        int col = nf * 8 + 2 * c;
        float2 lo = {O[nf][0], O[nf][1]};
        float2 hi = {O[nf][2], O[nf][3]};
        *(float2*)&pO[(wm + g) * DK + col]     = lo;
        *(float2*)&pO[(wm + g + 8) * DK + col] = hi;
    }
    if (c == 0) {
        float* ml = g_pml + slot * 256;
        ml[(wm + g) * 2]         = mr0;
        ml[(wm + g) * 2 + 1]     = l0;
        ml[(wm + g + 8) * 2]     = mr1;
        ml[(wm + g + 8) * 2 + 1] = l1;
    }
}

// ---------------------------------------------------------------------------
// Combine partial chunks -> g_O (normalized). Grid 64 = (b,qt), 256 threads.
// ---------------------------------------------------------------------------
__global__ __launch_bounds__(256) void combine_kernel()
{
    const int b = blockIdx.x >> 4, qt = blockIdx.x & 15;
    const int nch = qt / 4 + 1;
    int prefix = 0;
    for (int q = 0; q < qt; q++) prefix += q / 4 + 1;
    const int base = b * BPB + prefix;

    const int row = threadIdx.x >> 1;
    const int ch0 = (threadIdx.x & 1) * 64;

    float mv[4], lv[4], wgt[4];
    float M = -1e30f;
    for (int i = 0; i < nch; i++) {
        mv[i] = g_pml[(base + i) * 256 + row * 2];
        lv[i] = g_pml[(base + i) * 256 + row * 2 + 1];
        M = fmaxf(M, mv[i]);
    }
    float L = 0.f;
    for (int i = 0; i < nch; i++) { wgt[i] = __expf(mv[i] - M); L += wgt[i] * lv[i]; }
    const float invL = 1.f / L;

    const size_t orow = ((size_t)b * TT + qt * 128 + row) * DK;
#pragma unroll 4
    for (int j = 0; j < 64; j += 4) {
        float4 a = {0.f, 0.f, 0.f, 0.f};
        for (int i = 0; i < nch; i++) {
            float4 v = *(const float4*)&g_pO[((size_t)(base + i) * 128 + row) * DK + ch0 + j];
            a.x += wgt[i] * v.x; a.y += wgt[i] * v.y;
            a.z += wgt[i] * v.z; a.w += wgt[i] * v.w;
        }
        a.x *= invL; a.y *= invL; a.z *= invL; a.w *= invL;
        *(float4*)&g_O[orow + ch0 + j] = a;
    }
}

// ---------------------------------------------------------------------------
extern "C" void kernel_launch(void* const* d_in, const int* in_sizes, int n_in,
                              void* d_out, int out_size)
{
    const float* x  = (const float*)d_in[0];
    const float* Wq = (const float*)d_in[1];
    const float* Wk = (const float*)d_in[2];
    const float* Wv = (const float*)d_in[3];
    const float* Wo = (const float*)d_in[4];
    float* out = (float*)d_out;

    cudaFuncSetAttribute(flash_kernel,
                         cudaFuncAttributeMaxDynamicSharedMemorySize, FLASH_SMEM);

    // QKV projections (fp16 mma): [8192,1024] @ [1024,128] x3
    qkv_kernel<<<dim3(RR / 128, 1, 3), 256>>>(x, Wq, Wk, Wv);

    // Split-KV causal flash attention (fp16 mma, 2 blocks/SM)
    flash_kernel<<<NSLOT, 256, FLASH_SMEM>>>();

    // Merge partial softmax chunks
    combine_kernel<<<BB * 16, 256>>>();

    // Output projection: [8192,128] @ [128,1024]
    outproj_kernel<<<dim3(DD / 128, RR / 128), 256>>>(Wo, out);
}

// round 11
// speedup vs baseline: 1.4284x; 1.1743x over previous
#include <cuda_runtime.h>
#include <math.h>
#include <stdint.h>

#define BB 4
#define TT 2048
#define DD 1024
#define DK 128
#define RR (BB*TT)   // 8192

#define BKV 32
#define CHUNK 8             // KV tiles per flash block
#define BPB 72              // flash blocks per batch: sum_{q=0..15} ceil((4q+4)/8)
#define NSLOT (BB*BPB)      // 288 partial slots

// Scratch (device globals: allocation-free)
__device__ float    g_V[RR*DK];                 // V fp32 (pack source)
__device__ float    g_O[RR*DK];
__device__ unsigned g_Qh[RR*(DK/2)];            // Q fp16 packed half2, pre-scaled
__device__ unsigned g_Kh[RR*(DK/2)];            // K fp16 packed half2
__device__ unsigned g_Vp[(RR/2)*DK];            // V fp16, key-pair packed: [t2][d]
__device__ float    g_pO[(size_t)NSLOT*128*DK]; // partial O per chunk slot
__device__ float    g_pml[NSLOT*128*2];         // partial (m,l) per row

// pack two f32 -> half2 u32 (lo = first arg, hi = second arg)
__device__ __forceinline__ unsigned f2h2(float lo, float hi) {
    unsigned u;
    asm("cvt.rn.f16x2.f32 %0, %1, %2;" : "=r"(u) : "f"(hi), "f"(lo));
    return u;
}

__device__ __forceinline__ void mma_f16(float c[4],
    unsigned a0, unsigned a1, unsigned a2, unsigned a3,
    unsigned b0, unsigned b1)
{
    asm volatile(
        "mma.sync.aligned.m16n8k16.row.col.f32.f16.f16.f32 "
        "{%0,%1,%2,%3}, {%4,%5,%6,%7}, {%8,%9}, {%0,%1,%2,%3};"
        : "+f"(c[0]), "+f"(c[1]), "+f"(c[2]), "+f"(c[3])
        : "r"(a0), "r"(a1), "r"(a2), "r"(a3), "r"(b0), "r"(b1));
}

__device__ __forceinline__ uint32_t smem_u32(const void* p) {
    uint32_t a;
    asm("{ .reg .u64 t; cvta.to.shared.u64 t, %1; cvt.u32.u64 %0, t; }"
        : "=r"(a) : "l"(p));
    return a;
}

__device__ __forceinline__ void cp16(uint32_t dst, const void* src) {
    asm volatile("cp.async.ca.shared.global [%0], [%1], 16;"
                 :: "r"(dst), "l"(src) : "memory");
}
#define CP_COMMIT() asm volatile("cp.async.commit_group;" ::: "memory")
#define CP_WAIT0()  asm volatile("cp.async.wait_group 0;"  ::: "memory")

// ---------------------------------------------------------------------------
// fp16 GEMM: C[128x128 tile] = A[M,K] @ B[K,N], fp32 in, fp32 or packed-half2
// out. 256 threads = 8 warps as 2(m) x 4(n); warp tile 64x32; BK=32.
// As: [m][k2] packed half2, stride 20 u32. Bs: [k2][n] k-pair packed, str 136.
// Double-buffered + register prefetch, one barrier per slab.
// ---------------------------------------------------------------------------
#define AST 20
#define BST 136

__device__ __forceinline__ void gemm128_f16(
    const float* __restrict__ A, const float* __restrict__ Bw,
    float* __restrict__ C, unsigned* __restrict__ Ch, float oscale,
    int N, int K, int m0, int n0)
{
    __shared__ unsigned As[2 * 128 * AST];
    __shared__ unsigned Bs[2 * 16 * BST];

    const int tid = threadIdx.x, lane = tid & 31, w = tid >> 5;
    const int wm = (w >> 2) * 64, wn = (w & 3) * 32;
    const int g = lane >> 2, c = lane & 3;

    float acc[4][4][4];
#pragma unroll
    for (int mf = 0; mf < 4; mf++)
#pragma unroll
        for (int nf = 0; nf < 4; nf++)
#pragma unroll
            for (int j = 0; j < 4; j++) acc[mf][nf][j] = 0.f;

    const int arow = tid >> 1;
    const int aku  = (tid & 1) * 8;
    const int bk2 = tid >> 4;
    const int bn0 = (tid & 15) * 8;

    float4 av[4], bv[4];
#pragma unroll
    for (int i = 0; i < 4; i++)
        av[i] = *(const float4*)&A[(size_t)(m0 + arow) * K + aku * 2 + i * 4];
    bv[0] = *(const float4*)&Bw[(size_t)(2 * bk2)     * N + n0 + bn0];
    bv[1] = *(const float4*)&Bw[(size_t)(2 * bk2)     * N + n0 + bn0 + 4];
    bv[2] = *(const float4*)&Bw[(size_t)(2 * bk2 + 1) * N + n0 + bn0];
    bv[3] = *(const float4*)&Bw[(size_t)(2 * bk2 + 1) * N + n0 + bn0 + 4];

    int s = 0;
    for (int k0 = 0; k0 < K; k0 += 32) {
        unsigned* Ab = As + s * 128 * AST;
        unsigned* Bb = Bs + s * 16 * BST;
        {
            uint4 u0 = {f2h2(av[0].x, av[0].y), f2h2(av[0].z, av[0].w),
                        f2h2(av[1].x, av[1].y), f2h2(av[1].z, av[1].w)};
            uint4 u1 = {f2h2(av[2].x, av[2].y), f2h2(av[2].z, av[2].w),
                        f2h2(av[3].x, av[3].y), f2h2(av[3].z, av[3].w)};
            *(uint4*)&Ab[arow * AST + aku]     = u0;
            *(uint4*)&Ab[arow * AST + aku + 4] = u1;
        }
        {
            uint4 u0 = {f2h2(bv[0].x, bv[2].x), f2h2(bv[0].y, bv[2].y),
                        f2h2(bv[0].z, bv[2].z), f2h2(bv[0].w, bv[2].w)};
            uint4 u1 = {f2h2(bv[1].x, bv[3].x), f2h2(bv[1].y, bv[3].y),
                        f2h2(bv[1].z, bv[3].z), f2h2(bv[1].w, bv[3].w)};
            *(uint4*)&Bb[bk2 * BST + bn0]     = u0;
            *(uint4*)&Bb[bk2 * BST + bn0 + 4] = u1;
        }
        __syncthreads();

        if (k0 + 32 < K) {
#pragma unroll
            for (int i = 0; i < 4; i++)
                av[i] = *(const float4*)&A[(size_t)(m0 + arow) * K + k0 + 32 + aku * 2 + i * 4];
            bv[0] = *(const float4*)&Bw[(size_t)(k0 + 32 + 2 * bk2)     * N + n0 + bn0];
            bv[1] = *(const float4*)&Bw[(size_t)(k0 + 32 + 2 * bk2)     * N + n0 + bn0 + 4];
            bv[2] = *(const float4*)&Bw[(size_t)(k0 + 32 + 2 * bk2 + 1) * N + n0 + bn0];
            bv[3] = *(const float4*)&Bw[(size_t)(k0 + 32 + 2 * bk2 + 1) * N + n0 + bn0 + 4];
        }

#pragma unroll
        for (int ks = 0; ks < 2; ks++) {
            const int kk = ks * 8 + c;
            unsigned a[4][4], b[4][2];
#pragma unroll
            for (int mf = 0; mf < 4; mf++) {
                int r = wm + mf * 16 + g;
                a[mf][0] = Ab[r * AST + kk];
                a[mf][1] = Ab[(r + 8) * AST + kk];
                a[mf][2] = Ab[r * AST + kk + 4];
                a[mf][3] = Ab[(r + 8) * AST + kk + 4];
            }
#pragma unroll
            for (int nf = 0; nf < 4; nf++) {
                int n = wn + nf * 8 + g;
                b[nf][0] = Bb[kk * BST + n];
                b[nf][1] = Bb[(kk + 4) * BST + n];
            }
#pragma unroll
            for (int mf = 0; mf < 4; mf++)
#pragma unroll
                for (int nf = 0; nf < 4; nf++)
                    mma_f16(acc[mf][nf], a[mf][0], a[mf][1], a[mf][2], a[mf][3],
                            b[nf][0], b[nf][1]);
        }
        s ^= 1;
    }

    if (Ch) {
        // fp16 packed half2 output, optional scale folded in
#pragma unroll
        for (int mf = 0; mf < 4; mf++)
#pragma unroll
            for (int nf = 0; nf < 4; nf++) {
                int row  = m0 + wm + mf * 16 + g;
                int col2 = (n0 + wn + nf * 8) / 2 + c;
                Ch[(size_t)row * (N / 2) + col2] =
                    f2h2(acc[mf][nf][0] * oscale, acc[mf][nf][1] * oscale);
                Ch[(size_t)(row + 8) * (N / 2) + col2] =
                    f2h2(acc[mf][nf][2] * oscale, acc[mf][nf][3] * oscale);
            }
    } else {
#pragma unroll
        for (int mf = 0; mf < 4; mf++)
#pragma unroll
            for (int nf = 0; nf < 4; nf++) {
                size_t r0 = (size_t)(m0 + wm + mf * 16 + g) * N + n0 + wn + nf * 8 + 2 * c;
                float2 lo = {acc[mf][nf][0], acc[mf][nf][1]};
                float2 hi = {acc[mf][nf][2], acc[mf][nf][3]};
                *(float2*)&C[r0]                 = lo;
                *(float2*)&C[r0 + (size_t)8 * N] = hi;
            }
    }
}

__global__ __launch_bounds__(256) void qkv_kernel(
    const float* __restrict__ x, const float* __restrict__ Wq,
    const float* __restrict__ Wk, const float* __restrict__ Wv)
{
    const float scale = 0.08838834764831845f;   // 1/sqrt(128), folded into Q
    if (blockIdx.z == 0)
        gemm128_f16(x, Wq, nullptr, g_Qh, scale, DK, DD, blockIdx.x * 128, 0);
    else if (blockIdx.z == 1)
        gemm128_f16(x, Wk, nullptr, g_Kh, 1.0f, DK, DD, blockIdx.x * 128, 0);
    else
        gemm128_f16(x, Wv, g_V, nullptr, 1.0f, DK, DD, blockIdx.x * 128, 0);
}

__global__ __launch_bounds__(256) void outproj_kernel(
    const float* __restrict__ Wo, float* __restrict__ out)
{
    gemm128_f16(g_O, Wo, out, nullptr, 1.0f, DD, DK, blockIdx.y * 128, blockIdx.x * 128);
}

// ---------------------------------------------------------------------------
// Pack V fp32 -> fp16 key-pair packed: g_Vp[t2][d] = half2(V[2t2][d], V[2t2+1][d])
// ---------------------------------------------------------------------------
__global__ __launch_bounds__(256) void packv_kernel()
{
    const int idx = blockIdx.x * 256 + threadIdx.x;   // 131072 threads
    const int t2 = idx >> 5;
    const int n  = (idx & 31) * 4;
    float4 e = *(const float4*)&g_V[(size_t)(2 * t2) * DK + n];
    float4 o = *(const float4*)&g_V[(size_t)(2 * t2 + 1) * DK + n];
    uint4 u = {f2h2(e.x, o.x), f2h2(e.y, o.y), f2h2(e.z, o.z), f2h2(e.w, o.w)};
    *(uint4*)&g_Vp[(size_t)t2 * DK + n] = u;
}

// ---------------------------------------------------------------------------
// Flash attention, fp16 mma (m16n8k16), split-KV, cp.async staging.
// BQ=128, BKV=32, 256 threads = 8 warps (warp owns 16 q-rows), chunk = 8
// tiles -> 288 blocks = one full wave at 2 blocks/SM. Double-buffered K/V,
// ONE barrier per tile; all staging = plain 16B cp.async of pre-packed fp16.
// smem = 68 KB -> 2 blocks/SM.
// ---------------------------------------------------------------------------
#define QS2 68
#define KS2 68
#define VST 136
#define OFF_K (128*QS2)
#define OFF_V (OFF_K + 2*BKV*KS2)
#define FLASH_SMEM ((OFF_V + 2*16*VST) * 4)   // 69,632 bytes

__global__ __launch_bounds__(256, 2) void flash_kernel()
{
    extern __shared__ unsigned smf[];
    unsigned* Qs = smf;
    unsigned* Ks = smf + OFF_K;
    unsigned* Vs = smf + OFF_V;

    const int tid = threadIdx.x, lane = tid & 31, w = tid >> 5;
    const int g = lane >> 2, c = lane & 3;
    const int wm = w * 16;
    const uint32_t sbase = smem_u32(smf);

    // ---- schedule decode: reversed order puts big (qt) chunks first ----
    const int b  = blockIdx.x / BPB;
    const int wr = BPB - 1 - (blockIdx.x % BPB);
    int qt = 0, chunk = 0, prefix = 0;
    {
        int accn = 0;
        for (int q = 0; q < 16; q++) {
            int n = (q + 2) >> 1;              // ceil((4q+4)/8)
            if (wr < accn + n) { qt = q; chunk = wr - accn; prefix = accn; break; }
            accn += n;
        }
    }
    const int slot = b * BPB + prefix + chunk;
    const int q0 = qt * 128;
    const int it_total = 4 * qt + 4;
    const int t0 = chunk * CHUNK;
    const int tlen = (it_total - t0 < CHUNK) ? (it_total - t0) : CHUNK;

    const size_t bT  = (size_t)b * TT;
    const size_t bT2 = (size_t)b * (TT / 2);

    // staging indices
    const int kr = tid >> 3,  kku = (tid & 7) * 8;    // K: row, u32 group
    const int vk2 = tid >> 4, vn0 = (tid & 15) * 8;   // V: key-pair, n group
    const int qr = tid >> 1,  qku = (tid & 1) * 32;   // Q: row, u32 group

    auto stage = [&](int t, int s) {
        uint32_t kb = sbase + (OFF_K + s * BKV * KS2 + kr * KS2 + kku) * 4;
        const unsigned* ksrc = &g_Kh[(bT + (size_t)t * BKV + kr) * 64 + kku];
        cp16(kb,      ksrc);
        cp16(kb + 16, ksrc + 4);
        uint32_t vb = sbase + (OFF_V + s * 16 * VST + vk2 * VST + vn0) * 4;
        const unsigned* vsrc = &g_Vp[(bT2 + (size_t)t * 16 + vk2) * DK + vn0];
        cp16(vb,      vsrc);
        cp16(vb + 16, vsrc + 4);
    };

    // preload Q + first KV tile
    {
        const unsigned* qsrc = &g_Qh[(bT + q0 + qr) * 64 + qku];
        uint32_t qb = sbase + (qr * QS2 + qku) * 4;
#pragma unroll
        for (int i = 0; i < 8; i++)
            cp16(qb + i * 16, qsrc + i * 4);
        stage(t0, 0);
        CP_COMMIT();
        CP_WAIT0();
        __syncthreads();
    }

    float mr0 = -1e30f, mr1 = -1e30f, l0 = 0.f, l1 = 0.f;
    float O[16][4];
#pragma unroll
    for (int nf = 0; nf < 16; nf++)
#pragma unroll
        for (int j = 0; j < 4; j++) O[nf][j] = 0.f;

    int s = 0;
    for (int ti = 0; ti < tlen; ti++) {
        const int t = t0 + ti;
        unsigned* Kb = Ks + s * BKV * KS2;
        unsigned* Vb = Vs + s * 16 * VST;

        // stage next tile (cp.async overlaps all compute below)
        if (ti + 1 < tlen) { stage(t + 1, s ^ 1); CP_COMMIT(); }

        // --- S = Q K^T : warp 16x32, 4 n-frags, 8 k16-slices ---
        float sfr[4][4];
#pragma unroll
        for (int nf = 0; nf < 4; nf++)
#pragma unroll
            for (int j = 0; j < 4; j++) sfr[nf][j] = 0.f;

#pragma unroll
        for (int ks = 0; ks < 8; ks++) {
            const int kk = ks * 8 + c;
            unsigned a0 = Qs[(wm + g) * QS2 + kk];
            unsigned a1 = Qs[(wm + g + 8) * QS2 + kk];
            unsigned a2 = Qs[(wm + g) * QS2 + kk + 4];
            unsigned a3 = Qs[(wm + g + 8) * QS2 + kk + 4];
#pragma unroll
            for (int nf = 0; nf < 4; nf++) {
                int n = nf * 8 + g;
                mma_f16(sfr[nf], a0, a1, a2, a3,
                        Kb[n * KS2 + kk], Kb[n * KS2 + kk + 4]);
            }
        }

        // causal mask (scale pre-folded into Q)
        if (t * BKV + BKV - 1 > q0 + wm) {
            const int r0g = q0 + wm + g, r1g = r0g + 8;
#pragma unroll
            for (int nf = 0; nf < 4; nf++) {
                int col = t * BKV + nf * 8 + 2 * c;
                if (col     > r0g) sfr[nf][0] = -1e30f;
                if (col + 1 > r0g) sfr[nf][1] = -1e30f;
                if (col     > r1g) sfr[nf][2] = -1e30f;
                if (col + 1 > r1g) sfr[nf][3] = -1e30f;
            }
        }

        // --- online softmax (rows wm+g, wm+g+8; reduce over 4-lane quad) ---
        float rm0 = -1e30f, rm1 = -1e30f;
#pragma unroll
        for (int nf = 0; nf < 4; nf++) {
            rm0 = fmaxf(rm0, fmaxf(sfr[nf][0], sfr[nf][1]));
            rm1 = fmaxf(rm1, fmaxf(sfr[nf][2], sfr[nf][3]));
        }
        rm0 = fmaxf(rm0, __shfl_xor_sync(0xffffffffu, rm0, 1));
        rm0 = fmaxf(rm0, __shfl_xor_sync(0xffffffffu, rm0, 2));
        rm1 = fmaxf(rm1, __shfl_xor_sync(0xffffffffu, rm1, 1));
        rm1 = fmaxf(rm1, __shfl_xor_sync(0xffffffffu, rm1, 2));

        float mn0 = fmaxf(mr0, rm0), mn1 = fmaxf(mr1, rm1);
        float al0 = __expf(mr0 - mn0), al1 = __expf(mr1 - mn1);
        float sum0 = 0.f, sum1 = 0.f;
#pragma unroll
        for (int nf = 0; nf < 4; nf++) {
            sfr[nf][0] = __expf(sfr[nf][0] - mn0);
            sfr[nf][1] = __expf(sfr[nf][1] - mn0);
            sfr[nf][2] = __expf(sfr[nf][2] - mn1);
            sfr[nf][3] = __expf(sfr[nf][3] - mn1);
            sum0 += sfr[nf][0] + sfr[nf][1];
            sum1 += sfr[nf][2] + sfr[nf][3];
        }
        sum0 += __shfl_xor_sync(0xffffffffu, sum0, 1);
        sum0 += __shfl_xor_sync(0xffffffffu, sum0, 2);
        sum1 += __shfl_xor_sync(0xffffffffu, sum1, 1);
        sum1 += __shfl_xor_sync(0xffffffffu, sum1, 2);

        l0 = l0 * al0 + sum0; l1 = l1 * al1 + sum1;
        mr0 = mn0; mr1 = mn1;
#pragma unroll
        for (int nf = 0; nf < 16; nf++) {
            O[nf][0] *= al0; O[nf][1] *= al0;
            O[nf][2] *= al1; O[nf][3] *= al1;
        }

        // --- O += P V : S-frags pack directly into PV A-frags ---
#pragma unroll
        for (int ksl = 0; ksl < 2; ksl++) {
            unsigned a0 = f2h2(sfr[2 * ksl][0],     sfr[2 * ksl][1]);
            unsigned a1 = f2h2(sfr[2 * ksl][2],     sfr[2 * ksl][3]);
            unsigned a2 = f2h2(sfr[2 * ksl + 1][0], sfr[2 * ksl + 1][1]);
            unsigned a3 = f2h2(sfr[2 * ksl + 1][2], sfr[2 * ksl + 1][3]);
            const int kk = ksl * 8 + c;
#pragma unroll
            for (int nf = 0; nf < 16; nf++) {
                int n = nf * 8 + g;
                mma_f16(O[nf], a0, a1, a2, a3,
                        Vb[kk * VST + n], Vb[(kk + 4) * VST + n]);
            }
        }

        if (ti + 1 < tlen) CP_WAIT0();
        __syncthreads();
        s ^= 1;
    }

    // ---- write partial (unnormalized O, m, l) ----
    float* pO = g_pO + (size_t)slot * 128 * DK;
#pragma unroll
    for (int nf = 0; nf < 16; nf++) {
        int col = nf * 8 + 2 * c;
        float2 lo = {O[nf][0], O[nf][1]};
        float2 hi = {O[nf][2], O[nf][3]};
        *(float2*)&pO[(wm + g) * DK + col]     = lo;
        *(float2*)&pO[(wm + g + 8) * DK + col] = hi;
    }
    if (c == 0) {
        float* ml = g_pml + slot * 256;
        ml[(wm + g) * 2]         = mr0;
        ml[(wm + g) * 2 + 1]     = l0;
        ml[(wm + g + 8) * 2]     = mr1;
        ml[(wm + g + 8) * 2 + 1] = l1;
    }
}

// ---------------------------------------------------------------------------
// Combine partial chunks -> g_O (normalized). Grid 64 = (b,qt), 256 threads.
// ---------------------------------------------------------------------------
__global__ __launch_bounds__(256) void combine_kernel()
{
    const int b = blockIdx.x >> 4, qt = blockIdx.x & 15;
    const int nch = (qt + 2) >> 1;             // ceil((4qt+4)/8)
    int prefix = 0;
    for (int q = 0; q < qt; q++) prefix += (q + 2) >> 1;
    const int base = b * BPB + prefix;

    const int row = threadIdx.x >> 1;
    const int ch0 = (threadIdx.x & 1) * 64;

    float mv[8], lv[8], wgt[8];
    float M = -1e30f;
    for (int i = 0; i < nch; i++) {
        mv[i] = g_pml[(base + i) * 256 + row * 2];
        lv[i] = g_pml[(base + i) * 256 + row * 2 + 1];
        M = fmaxf(M, mv[i]);
    }
    float L = 0.f;
    for (int i = 0; i < nch; i++) { wgt[i] = __expf(mv[i] - M); L += wgt[i] * lv[i]; }
    const float invL = 1.f / L;

    const size_t orow = ((size_t)b * TT + qt * 128 + row) * DK;
#pragma unroll 4
    for (int j = 0; j < 64; j += 4) {
        float4 a = {0.f, 0.f, 0.f, 0.f};
        for (int i = 0; i < nch; i++) {
            float4 v = *(const float4*)&g_pO[((size_t)(base + i) * 128 + row) * DK + ch0 + j];
            a.x += wgt[i] * v.x; a.y += wgt[i] * v.y;
            a.z += wgt[i] * v.z; a.w += wgt[i] * v.w;
        }
        a.x *= invL; a.y *= invL; a.z *= invL; a.w *= invL;
        *(float4*)&g_O[orow + ch0 + j] = a;
    }
}

// ---------------------------------------------------------------------------
extern "C" void kernel_launch(void* const* d_in, const int* in_sizes, int n_in,
                              void* d_out, int out_size)
{
    const float* x  = (const float*)d_in[0];
    const float* Wq = (const float*)d_in[1];
    const float* Wk = (const float*)d_in[2];
    const float* Wv = (const float*)d_in[3];
    const float* Wo = (const float*)d_in[4];
    float* out = (float*)d_out;

    cudaFuncSetAttribute(flash_kernel,
                         cudaFuncAttributeMaxDynamicSharedMemorySize, FLASH_SMEM);

    // QKV projections (fp16 mma): Q/K written as packed fp16, V as fp32
    qkv_kernel<<<dim3(RR / 128, 1, 3), 256>>>(x, Wq, Wk, Wv);

    // Pack V into fp16 key-pair layout for flash's B operand
    packv_kernel<<<(RR / 2) * (DK / 4) / 256, 256>>>();

    // Split-KV causal flash attention (288 blocks = full wave at 2/SM)
    flash_kernel<<<NSLOT, 256, FLASH_SMEM>>>();

    // Merge partial softmax chunks
    combine_kernel<<<BB * 16, 256>>>();

    // Output projection: [8192,128] @ [128,1024]
    outproj_kernel<<<dim3(DD / 128, RR / 128), 256>>>(Wo, out);
}

// round 12
// speedup vs baseline: 1.8439x; 1.2909x over previous
#include <cuda_runtime.h>
#include <math.h>
#include <stdint.h>

#define BB 4
#define TT 2048
#define DD 1024
#define DK 128
#define RR (BB*TT)   // 8192

#define BKV 32
#define CHUNK 8             // KV tiles per flash block
#define BPB 72              // flash blocks per batch: sum_{q=0..15} ceil((4q+4)/8)
#define NSLOT (BB*BPB)      // 288 partial slots

// Scratch (device globals: allocation-free)
__device__ float    g_V[RR*DK];                 // V fp32 (pack source)
__device__ unsigned g_Qh[RR*(DK/2)];            // Q fp16 packed half2, pre-scaled
__device__ unsigned g_Kh[RR*(DK/2)];            // K fp16 packed half2
__device__ unsigned g_Vp[(RR/2)*DK];            // V fp16, key-pair packed: [t2][d]
__device__ unsigned g_Oh[RR*(DK/2)];            // attention O, fp16 packed half2
__device__ float    g_pO[(size_t)NSLOT*128*DK]; // partial O per chunk slot
__device__ float    g_pml[NSLOT*128*2];         // partial (m,l) per row

// pack two f32 -> half2 u32 (lo = first arg, hi = second arg)
__device__ __forceinline__ unsigned f2h2(float lo, float hi) {
    unsigned u;
    asm("cvt.rn.f16x2.f32 %0, %1, %2;" : "=r"(u) : "f"(hi), "f"(lo));
    return u;
}

__device__ __forceinline__ void mma_f16(float c[4],
    unsigned a0, unsigned a1, unsigned a2, unsigned a3,
    unsigned b0, unsigned b1)
{
    asm volatile(
        "mma.sync.aligned.m16n8k16.row.col.f32.f16.f16.f32 "
        "{%0,%1,%2,%3}, {%4,%5,%6,%7}, {%8,%9}, {%0,%1,%2,%3};"
        : "+f"(c[0]), "+f"(c[1]), "+f"(c[2]), "+f"(c[3])
        : "r"(a0), "r"(a1), "r"(a2), "r"(a3), "r"(b0), "r"(b1));
}

__device__ __forceinline__ uint32_t smem_u32(const void* p) {
    uint32_t a;
    asm("{ .reg .u64 t; cvta.to.shared.u64 t, %1; cvt.u32.u64 %0, t; }"
        : "=r"(a) : "l"(p));
    return a;
}

__device__ __forceinline__ void cp16(uint32_t dst, const void* src) {
    asm volatile("cp.async.ca.shared.global [%0], [%1], 16;"
                 :: "r"(dst), "l"(src) : "memory");
}
#define CP_COMMIT() asm volatile("cp.async.commit_group;" ::: "memory")
#define CP_WAIT0()  asm volatile("cp.async.wait_group 0;"  ::: "memory")

// ---------------------------------------------------------------------------
// fp16 GEMM: C[128x128 tile] = A[M,K] @ B[K,N]; A either fp32 (converted at
// staging) or pre-packed half2 (Ah). Output fp32 (C) or packed half2 (Ch).
// 256 threads = 8 warps as 2(m) x 4(n); warp tile 64x32; BK=32.
// As: [m][k2] packed half2, stride 20 u32. Bs: [k2][n] k-pair packed, str 136.
// Double-buffered + register prefetch, one barrier per slab.
// ---------------------------------------------------------------------------
#define AST 20
#define BST 136

__device__ __forceinline__ void gemm128_f16(
    const float* __restrict__ A, const unsigned* __restrict__ Ah,
    const float* __restrict__ Bw,
    float* __restrict__ C, unsigned* __restrict__ Ch, float oscale,
    int N, int K, int m0, int n0)
{
    __shared__ unsigned As[2 * 128 * AST];
    __shared__ unsigned Bs[2 * 16 * BST];

    const int tid = threadIdx.x, lane = tid & 31, w = tid >> 5;
    const int wm = (w >> 2) * 64, wn = (w & 3) * 32;
    const int g = lane >> 2, c = lane & 3;

    float acc[4][4][4];
#pragma unroll
    for (int mf = 0; mf < 4; mf++)
#pragma unroll
        for (int nf = 0; nf < 4; nf++)
#pragma unroll
            for (int j = 0; j < 4; j++) acc[mf][nf][j] = 0.f;

    const int arow = tid >> 1;
    const int aku  = (tid & 1) * 8;       // u32 offset within 16-u32 slab row
    const int bk2 = tid >> 4;
    const int bn0 = (tid & 15) * 8;

    float4 av[4];
    uint4  ah[2];
    float4 bv[4];
    if (Ah) {
        ah[0] = *(const uint4*)&Ah[(size_t)(m0 + arow) * (K / 2) + aku];
        ah[1] = *(const uint4*)&Ah[(size_t)(m0 + arow) * (K / 2) + aku + 4];
    } else {
#pragma unroll
        for (int i = 0; i < 4; i++)
            av[i] = *(const float4*)&A[(size_t)(m0 + arow) * K + aku * 2 + i * 4];
    }
    bv[0] = *(const float4*)&Bw[(size_t)(2 * bk2)     * N + n0 + bn0];
    bv[1] = *(const float4*)&Bw[(size_t)(2 * bk2)     * N + n0 + bn0 + 4];
    bv[2] = *(const float4*)&Bw[(size_t)(2 * bk2 + 1) * N + n0 + bn0];
    bv[3] = *(const float4*)&Bw[(size_t)(2 * bk2 + 1) * N + n0 + bn0 + 4];

    int s = 0;
    for (int k0 = 0; k0 < K; k0 += 32) {
        unsigned* Ab = As + s * 128 * AST;
        unsigned* Bb = Bs + s * 16 * BST;
        if (Ah) {
            *(uint4*)&Ab[arow * AST + aku]     = ah[0];
            *(uint4*)&Ab[arow * AST + aku + 4] = ah[1];
        } else {
            uint4 u0 = {f2h2(av[0].x, av[0].y), f2h2(av[0].z, av[0].w),
                        f2h2(av[1].x, av[1].y), f2h2(av[1].z, av[1].w)};
            uint4 u1 = {f2h2(av[2].x, av[2].y), f2h2(av[2].z, av[2].w),
                        f2h2(av[3].x, av[3].y), f2h2(av[3].z, av[3].w)};
            *(uint4*)&Ab[arow * AST + aku]     = u0;
            *(uint4*)&Ab[arow * AST + aku + 4] = u1;
        }
        {
            uint4 u0 = {f2h2(bv[0].x, bv[2].x), f2h2(bv[0].y, bv[2].y),
                        f2h2(bv[0].z, bv[2].z), f2h2(bv[0].w, bv[2].w)};
            uint4 u1 = {f2h2(bv[1].x, bv[3].x), f2h2(bv[1].y, bv[3].y),
                        f2h2(bv[1].z, bv[3].z), f2h2(bv[1].w, bv[3].w)};
            *(uint4*)&Bb[bk2 * BST + bn0]     = u0;
            *(uint4*)&Bb[bk2 * BST + bn0 + 4] = u1;
        }
        __syncthreads();

        if (k0 + 32 < K) {
            if (Ah) {
                ah[0] = *(const uint4*)&Ah[(size_t)(m0 + arow) * (K / 2) + (k0 + 32) / 2 + aku];
                ah[1] = *(const uint4*)&Ah[(size_t)(m0 + arow) * (K / 2) + (k0 + 32) / 2 + aku + 4];
            } else {
#pragma unroll
                for (int i = 0; i < 4; i++)
                    av[i] = *(const float4*)&A[(size_t)(m0 + arow) * K + k0 + 32 + aku * 2 + i * 4];
            }
            bv[0] = *(const float4*)&Bw[(size_t)(k0 + 32 + 2 * bk2)     * N + n0 + bn0];
            bv[1] = *(const float4*)&Bw[(size_t)(k0 + 32 + 2 * bk2)     * N + n0 + bn0 + 4];
            bv[2] = *(const float4*)&Bw[(size_t)(k0 + 32 + 2 * bk2 + 1) * N + n0 + bn0];
            bv[3] = *(const float4*)&Bw[(size_t)(k0 + 32 + 2 * bk2 + 1) * N + n0 + bn0 + 4];
        }

#pragma unroll
        for (int ks = 0; ks < 2; ks++) {
            const int kk = ks * 8 + c;
            unsigned a[4][4], b[4][2];
#pragma unroll
            for (int mf = 0; mf < 4; mf++) {
                int r = wm + mf * 16 + g;
                a[mf][0] = Ab[r * AST + kk];
                a[mf][1] = Ab[(r + 8) * AST + kk];
                a[mf][2] = Ab[r * AST + kk + 4];
                a[mf][3] = Ab[(r + 8) * AST + kk + 4];
            }
#pragma unroll
            for (int nf = 0; nf < 4; nf++) {
                int n = wn + nf * 8 + g;
                b[nf][0] = Bb[kk * BST + n];
                b[nf][1] = Bb[(kk + 4) * BST + n];
            }
#pragma unroll
            for (int mf = 0; mf < 4; mf++)
#pragma unroll
                for (int nf = 0; nf < 4; nf++)
                    mma_f16(acc[mf][nf], a[mf][0], a[mf][1], a[mf][2], a[mf][3],
                            b[nf][0], b[nf][1]);
        }
        s ^= 1;
    }

    if (Ch) {
#pragma unroll
        for (int mf = 0; mf < 4; mf++)
#pragma unroll
            for (int nf = 0; nf < 4; nf++) {
                int row  = m0 + wm + mf * 16 + g;
                int col2 = (n0 + wn + nf * 8) / 2 + c;
                Ch[(size_t)row * (N / 2) + col2] =
                    f2h2(acc[mf][nf][0] * oscale, acc[mf][nf][1] * oscale);
                Ch[(size_t)(row + 8) * (N / 2) + col2] =
                    f2h2(acc[mf][nf][2] * oscale, acc[mf][nf][3] * oscale);
            }
    } else {
#pragma unroll
        for (int mf = 0; mf < 4; mf++)
#pragma unroll
            for (int nf = 0; nf < 4; nf++) {
                size_t r0 = (size_t)(m0 + wm + mf * 16 + g) * N + n0 + wn + nf * 8 + 2 * c;
                float2 lo = {acc[mf][nf][0], acc[mf][nf][1]};
                float2 hi = {acc[mf][nf][2], acc[mf][nf][3]};
                *(float2*)&C[r0]                 = lo;
                *(float2*)&C[r0 + (size_t)8 * N] = hi;
            }
    }
}

__global__ __launch_bounds__(256) void qkv_kernel(
    const float* __restrict__ x, const float* __restrict__ Wq,
    const float* __restrict__ Wk, const float* __restrict__ Wv)
{
    const float scale = 0.08838834764831845f;   // 1/sqrt(128), folded into Q
    if (blockIdx.z == 0)
        gemm128_f16(x, nullptr, Wq, nullptr, g_Qh, scale, DK, DD, blockIdx.x * 128, 0);
    else if (blockIdx.z == 1)
        gemm128_f16(x, nullptr, Wk, nullptr, g_Kh, 1.0f, DK, DD, blockIdx.x * 128, 0);
    else
        gemm128_f16(x, nullptr, Wv, g_V, nullptr, 1.0f, DK, DD, blockIdx.x * 128, 0);
}

__global__ __launch_bounds__(256) void outproj_kernel(
    const float* __restrict__ Wo, float* __restrict__ out)
{
    gemm128_f16(nullptr, g_Oh, Wo, out, nullptr, 1.0f, DD, DK,
                blockIdx.y * 128, blockIdx.x * 128);
}

// ---------------------------------------------------------------------------
// Pack V fp32 -> fp16 key-pair packed: g_Vp[t2][d] = half2(V[2t2][d], V[2t2+1][d])
// ---------------------------------------------------------------------------
__global__ __launch_bounds__(256) void packv_kernel()
{
    const int idx = blockIdx.x * 256 + threadIdx.x;   // 131072 threads
    const int t2 = idx >> 5;
    const int n  = (idx & 31) * 4;
    float4 e = *(const float4*)&g_V[(size_t)(2 * t2) * DK + n];
    float4 o = *(const float4*)&g_V[(size_t)(2 * t2 + 1) * DK + n];
    uint4 u = {f2h2(e.x, o.x), f2h2(e.y, o.y), f2h2(e.z, o.z), f2h2(e.w, o.w)};
    *(uint4*)&g_Vp[(size_t)t2 * DK + n] = u;
}

// ---------------------------------------------------------------------------
// Flash attention, fp16 mma (m16n8k16), split-KV, cp.async staging.
// BQ=128, BKV=32, 256 threads = 8 warps (warp owns 16 q-rows), chunk = 8
// tiles -> 288 blocks = one full wave at 2 blocks/SM. Double-buffered K/V,
// ONE barrier per tile; all staging = plain 16B cp.async of pre-packed fp16.
// smem = 68 KB -> 2 blocks/SM.
// ---------------------------------------------------------------------------
#define QS2 68
#define KS2 68
#define VST 136
#define OFF_K (128*QS2)
#define OFF_V (OFF_K + 2*BKV*KS2)
#define FLASH_SMEM ((OFF_V + 2*16*VST) * 4)   // 69,632 bytes

__global__ __launch_bounds__(256, 2) void flash_kernel()
{
    extern __shared__ unsigned smf[];
    unsigned* Qs = smf;
    unsigned* Ks = smf + OFF_K;
    unsigned* Vs = smf + OFF_V;

    const int tid = threadIdx.x, lane = tid & 31, w = tid >> 5;
    const int g = lane >> 2, c = lane & 3;
    const int wm = w * 16;
    const uint32_t sbase = smem_u32(smf);

    // ---- schedule decode: reversed order puts big (qt) chunks first ----
    const int b  = blockIdx.x / BPB;
    const int wr = BPB - 1 - (blockIdx.x % BPB);
    int qt = 0, chunk = 0, prefix = 0;
    {
        int accn = 0;
        for (int q = 0; q < 16; q++) {
            int n = (q + 2) >> 1;              // ceil((4q+4)/8)
            if (wr < accn + n) { qt = q; chunk = wr - accn; prefix = accn; break; }
            accn += n;
        }
    }
    const int slot = b * BPB + prefix + chunk;
    const int q0 = qt * 128;
    const int it_total = 4 * qt + 4;
    const int t0 = chunk * CHUNK;
    const int tlen = (it_total - t0 < CHUNK) ? (it_total - t0) : CHUNK;

    const size_t bT  = (size_t)b * TT;
    const size_t bT2 = (size_t)b * (TT / 2);

    // staging indices
    const int kr = tid >> 3,  kku = (tid & 7) * 8;    // K: row, u32 group
    const int vk2 = tid >> 4, vn0 = (tid & 15) * 8;   // V: key-pair, n group
    const int qr = tid >> 1,  qku = (tid & 1) * 32;   // Q: row, u32 group

    auto stage = [&](int t, int s) {
        uint32_t kb = sbase + (OFF_K + s * BKV * KS2 + kr * KS2 + kku) * 4;
        const unsigned* ksrc = &g_Kh[(bT + (size_t)t * BKV + kr) * 64 + kku];
        cp16(kb,      ksrc);
        cp16(kb + 16, ksrc + 4);
        uint32_t vb = sbase + (OFF_V + s * 16 * VST + vk2 * VST + vn0) * 4;
        const unsigned* vsrc = &g_Vp[(bT2 + (size_t)t * 16 + vk2) * DK + vn0];
        cp16(vb,      vsrc);
        cp16(vb + 16, vsrc + 4);
    };

    // preload Q + first KV tile
    {
        const unsigned* qsrc = &g_Qh[(bT + q0 + qr) * 64 + qku];
        uint32_t qb = sbase + (qr * QS2 + qku) * 4;
#pragma unroll
        for (int i = 0; i < 8; i++)
            cp16(qb + i * 16, qsrc + i * 4);
        stage(t0, 0);
        CP_COMMIT();
        CP_WAIT0();
        __syncthreads();
    }

    float mr0 = -1e30f, mr1 = -1e30f, l0 = 0.f, l1 = 0.f;
    float O[16][4];
#pragma unroll
    for (int nf = 0; nf < 16; nf++)
#pragma unroll
        for (int j = 0; j < 4; j++) O[nf][j] = 0.f;

    int s = 0;
    for (int ti = 0; ti < tlen; ti++) {
        const int t = t0 + ti;
        unsigned* Kb = Ks + s * BKV * KS2;
        unsigned* Vb = Vs + s * 16 * VST;

        // stage next tile (cp.async overlaps all compute below)
        if (ti + 1 < tlen) { stage(t + 1, s ^ 1); CP_COMMIT(); }

        // --- S = Q K^T : warp 16x32, 4 n-frags, 8 k16-slices ---
        float sfr[4][4];
#pragma unroll
        for (int nf = 0; nf < 4; nf++)
#pragma unroll
            for (int j = 0; j < 4; j++) sfr[nf][j] = 0.f;

#pragma unroll
        for (int ks = 0; ks < 8; ks++) {
            const int kk = ks * 8 + c;
            unsigned a0 = Qs[(wm + g) * QS2 + kk];
            unsigned a1 = Qs[(wm + g + 8) * QS2 + kk];
            unsigned a2 = Qs[(wm + g) * QS2 + kk + 4];
            unsigned a3 = Qs[(wm + g + 8) * QS2 + kk + 4];
#pragma unroll
            for (int nf = 0; nf < 4; nf++) {
                int n = nf * 8 + g;
                mma_f16(sfr[nf], a0, a1, a2, a3,
                        Kb[n * KS2 + kk], Kb[n * KS2 + kk + 4]);
            }
        }

        // causal mask (scale pre-folded into Q)
        if (t * BKV + BKV - 1 > q0 + wm) {
            const int r0g = q0 + wm + g, r1g = r0g + 8;
#pragma unroll
            for (int nf = 0; nf < 4; nf++) {
                int col = t * BKV + nf * 8 + 2 * c;
                if (col     > r0g) sfr[nf][0] = -1e30f;
                if (col + 1 > r0g) sfr[nf][1] = -1e30f;
                if (col     > r1g) sfr[nf][2] = -1e30f;
                if (col + 1 > r1g) sfr[nf][3] = -1e30f;
            }
        }

        // --- online softmax (rows wm+g, wm+g+8; reduce over 4-lane quad) ---
        float rm0 = -1e30f, rm1 = -1e30f;
#pragma unroll
        for (int nf = 0; nf < 4; nf++) {
            rm0 = fmaxf(rm0, fmaxf(sfr[nf][0], sfr[nf][1]));
            rm1 = fmaxf(rm1, fmaxf(sfr[nf][2], sfr[nf][3]));
        }
        rm0 = fmaxf(rm0, __shfl_xor_sync(0xffffffffu, rm0, 1));
        rm0 = fmaxf(rm0, __shfl_xor_sync(0xffffffffu, rm0, 2));
        rm1 = fmaxf(rm1, __shfl_xor_sync(0xffffffffu, rm1, 1));
        rm1 = fmaxf(rm1, __shfl_xor_sync(0xffffffffu, rm1, 2));

        float mn0 = fmaxf(mr0, rm0), mn1 = fmaxf(mr1, rm1);
        float al0 = __expf(mr0 - mn0), al1 = __expf(mr1 - mn1);
        float sum0 = 0.f, sum1 = 0.f;
#pragma unroll
        for (int nf = 0; nf < 4; nf++) {
            sfr[nf][0] = __expf(sfr[nf][0] - mn0);
            sfr[nf][1] = __expf(sfr[nf][1] - mn0);
            sfr[nf][2] = __expf(sfr[nf][2] - mn1);
            sfr[nf][3] = __expf(sfr[nf][3] - mn1);
            sum0 += sfr[nf][0] + sfr[nf][1];
            sum1 += sfr[nf][2] + sfr[nf][3];
        }
        sum0 += __shfl_xor_sync(0xffffffffu, sum0, 1);
        sum0 += __shfl_xor_sync(0xffffffffu, sum0, 2);
        sum1 += __shfl_xor_sync(0xffffffffu, sum1, 1);
        sum1 += __shfl_xor_sync(0xffffffffu, sum1, 2);

        l0 = l0 * al0 + sum0; l1 = l1 * al1 + sum1;
        mr0 = mn0; mr1 = mn1;
#pragma unroll
        for (int nf = 0; nf < 16; nf++) {
            O[nf][0] *= al0; O[nf][1] *= al0;
            O[nf][2] *= al1; O[nf][3] *= al1;
        }

        // --- O += P V : S-frags pack directly into PV A-frags ---
#pragma unroll
        for (int ksl = 0; ksl < 2; ksl++) {
            unsigned a0 = f2h2(sfr[2 * ksl][0],     sfr[2 * ksl][1]);
            unsigned a1 = f2h2(sfr[2 * ksl][2],     sfr[2 * ksl][3]);
            unsigned a2 = f2h2(sfr[2 * ksl + 1][0], sfr[2 * ksl + 1][1]);
            unsigned a3 = f2h2(sfr[2 * ksl + 1][2], sfr[2 * ksl + 1][3]);
            const int kk = ksl * 8 + c;
#pragma unroll
            for (int nf = 0; nf < 16; nf++) {
                int n = nf * 8 + g;
                mma_f16(O[nf], a0, a1, a2, a3,
                        Vb[kk * VST + n], Vb[(kk + 4) * VST + n]);
            }
        }

        if (ti + 1 < tlen) CP_WAIT0();
        __syncthreads();
        s ^= 1;
    }

    // ---- write partial (unnormalized O, m, l) ----
    float* pO = g_pO + (size_t)slot * 128 * DK;
#pragma unroll
    for (int nf = 0; nf < 16; nf++) {
        int col = nf * 8 + 2 * c;
        float2 lo = {O[nf][0], O[nf][1]};
        float2 hi = {O[nf][2], O[nf][3]};
        *(float2*)&pO[(wm + g) * DK + col]     = lo;
        *(float2*)&pO[(wm + g + 8) * DK + col] = hi;
    }
    if (c == 0) {
        float* ml = g_pml + slot * 256;
        ml[(wm + g) * 2]         = mr0;
        ml[(wm + g) * 2 + 1]     = l0;
        ml[(wm + g + 8) * 2]     = mr1;
        ml[(wm + g + 8) * 2 + 1] = l1;
    }
}

// ---------------------------------------------------------------------------
// Combine partial chunks -> g_Oh (normalized, packed fp16).
// One thread per (b, qt, row, 4 cols): 262144 threads, 1024 blocks.
// Two-pass over chunks (no register arrays -> no local-mem spills).
// ---------------------------------------------------------------------------
__global__ __launch_bounds__(256) void combine_kernel()
{
    const int idx  = blockIdx.x * 256 + threadIdx.x;
    const int col4 = (idx & 31) * 4;
    const int row  = (idx >> 5) & 127;
    const int bqt  = idx >> 12;            // 0..63
    const int b = bqt >> 4, qt = bqt & 15;
    const int nch = (qt + 2) >> 1;         // ceil((4qt+4)/8)
    int prefix = 0;
#pragma unroll
    for (int q = 0; q < 16; q++)
        if (q < qt) prefix += (q + 2) >> 1;
    const int base = b * BPB + prefix;

    // pass 1: global max m
    float M = -1e30f;
    for (int i = 0; i < nch; i++)
        M = fmaxf(M, g_pml[(base + i) * 256 + row * 2]);

    // pass 2: weighted accumulate
    float L = 0.f;
    float4 a = {0.f, 0.f, 0.f, 0.f};
    for (int i = 0; i < nch; i++) {
        float mi = g_pml[(base + i) * 256 + row * 2];
        float li = g_pml[(base + i) * 256 + row * 2 + 1];
        float wgt = __expf(mi - M);
        L += wgt * li;
        float4 v = *(const float4*)&g_pO[((size_t)(base + i) * 128 + row) * DK + col4];
        a.x += wgt * v.x; a.y += wgt * v.y;
        a.z += wgt * v.z; a.w += wgt * v.w;
    }
    const float invL = 1.f / L;
    const size_t orow = (size_t)b * TT + qt * 128 + row;
    g_Oh[orow * 64 + col4 / 2]     = f2h2(a.x * invL, a.y * invL);
    g_Oh[orow * 64 + col4 / 2 + 1] = f2h2(a.z * invL, a.w * invL);
}

// ---------------------------------------------------------------------------
extern "C" void kernel_launch(void* const* d_in, const int* in_sizes, int n_in,
                              void* d_out, int out_size)
{
    const float* x  = (const float*)d_in[0];
    const float* Wq = (const float*)d_in[1];
    const float* Wk = (const float*)d_in[2];
    const float* Wv = (const float*)d_in[3];
    const float* Wo = (const float*)d_in[4];
    float* out = (float*)d_out;

    cudaFuncSetAttribute(flash_kernel,
                         cudaFuncAttributeMaxDynamicSharedMemorySize, FLASH_SMEM);

    // QKV projections (fp16 mma): Q/K written as packed fp16, V as fp32
    qkv_kernel<<<dim3(RR / 128, 1, 3), 256>>>(x, Wq, Wk, Wv);

    // Pack V into fp16 key-pair layout for flash's B operand
    packv_kernel<<<(RR / 2) * (DK / 4) / 256, 256>>>();

    // Split-KV causal flash attention (288 blocks = full wave at 2/SM)
    flash_kernel<<<NSLOT, 256, FLASH_SMEM>>>();

    // Merge partial softmax chunks -> packed fp16 O (1024 blocks)
    combine_kernel<<<RR * 32 / 256, 256>>>();

    // Output projection: [8192,128] @ [128,1024], A pre-packed fp16
    outproj_kernel<<<dim3(DD / 128, RR / 128), 256>>>(Wo, out);
}

// round 13
// speedup vs baseline: 1.9524x; 1.0589x over previous
#include <cuda_runtime.h>
#include <cuda_fp16.h>
#include <math.h>
#include <stdint.h>

#define BB 4
#define TT 2048
#define DD 1024
#define DK 128
#define RR (BB*TT)   // 8192

#define BKV 32
#define CHUNK 8             // KV tiles per flash block
#define BPB 72              // flash blocks per batch: sum_{q=0..15} ceil((4q+4)/8)
#define NSLOT (BB*BPB)      // 288 partial slots

// Scratch (device globals: allocation-free)
__device__ unsigned g_Qh[RR*(DK/2)];            // Q fp16 packed half2, pre-scaled
__device__ unsigned g_Kh[RR*(DK/2)];            // K fp16 packed half2
__device__ unsigned g_Vp[(RR/2)*DK];            // V fp16, key-pair packed: [t2][d]
__device__ unsigned g_Oh[RR*(DK/2)];            // attention O, fp16 packed half2
__device__ unsigned g_pOh[(size_t)NSLOT*128*(DK/2)]; // partial O, fp16 packed
__device__ float    g_pml[NSLOT*128*2];         // partial (m,l) per row

// pack two f32 -> half2 u32 (lo = first arg, hi = second arg)
__device__ __forceinline__ unsigned f2h2(float lo, float hi) {
    unsigned u;
    asm("cvt.rn.f16x2.f32 %0, %1, %2;" : "=r"(u) : "f"(hi), "f"(lo));
    return u;
}

__device__ __forceinline__ float2 h2f2(unsigned u) {
    __half2 h = *(__half2*)&u;
    return __half22float2(h);
}

__device__ __forceinline__ void mma_f16(float c[4],
    unsigned a0, unsigned a1, unsigned a2, unsigned a3,
    unsigned b0, unsigned b1)
{
    asm volatile(
        "mma.sync.aligned.m16n8k16.row.col.f32.f16.f16.f32 "
        "{%0,%1,%2,%3}, {%4,%5,%6,%7}, {%8,%9}, {%0,%1,%2,%3};"
        : "+f"(c[0]), "+f"(c[1]), "+f"(c[2]), "+f"(c[3])
        : "r"(a0), "r"(a1), "r"(a2), "r"(a3), "r"(b0), "r"(b1));
}

__device__ __forceinline__ void ldmx4(unsigned* r, uint32_t addr) {
    asm volatile("ldmatrix.sync.aligned.m8n8.x4.shared.b16 {%0,%1,%2,%3}, [%4];"
        : "=r"(r[0]), "=r"(r[1]), "=r"(r[2]), "=r"(r[3]) : "r"(addr));
}

__device__ __forceinline__ uint32_t smem_u32(const void* p) {
    uint32_t a;
    asm("{ .reg .u64 t; cvta.to.shared.u64 t, %1; cvt.u32.u64 %0, t; }"
        : "=r"(a) : "l"(p));
    return a;
}

__device__ __forceinline__ void cp16(uint32_t dst, const void* src) {
    asm volatile("cp.async.ca.shared.global [%0], [%1], 16;"
                 :: "r"(dst), "l"(src) : "memory");
}
#define CP_COMMIT() asm volatile("cp.async.commit_group;" ::: "memory")
#define CP_WAIT0()  asm volatile("cp.async.wait_group 0;"  ::: "memory")

// ---------------------------------------------------------------------------
// fp16 GEMM: C[128x128 tile] = A[M,K] @ B[K,N]; A either fp32 (converted at
// staging) or pre-packed half2 (Ah). mode: 0 = fp32 C out, 1 = half2 Ch out
// (oscale folded), 2 = V key-pair packed out to g_Vp.
// 256 threads = 8 warps as 2(m) x 4(n); warp tile 64x32; BK=32.
// As: [m][k2] packed half2, stride 20 u32 (ldmatrix-compatible, conflict-free).
// Bs: [k2][n] k-pair packed, stride 136. A-frag loads via ldmatrix.x4.
// ---------------------------------------------------------------------------
#define AST 20
#define BST 136

__device__ __forceinline__ void gemm128_f16(
    const float* __restrict__ A, const unsigned* __restrict__ Ah,
    const float* __restrict__ Bw,
    float* __restrict__ C, unsigned* __restrict__ Ch, float oscale, int mode,
    int N, int K, int m0, int n0)
{
    __shared__ __align__(16) unsigned As[2 * 128 * AST];
    __shared__ __align__(16) unsigned Bs[2 * 16 * BST];

    const int tid = threadIdx.x, lane = tid & 31, w = tid >> 5;
    const int wm = (w >> 2) * 64, wn = (w & 3) * 32;
    const int g = lane >> 2, c = lane & 3;
    const uint32_t as_base = smem_u32(As);
    const int lm_row = lane & 15;            // ldmatrix source row
    const int lm_k   = (lane >> 4) * 4;      // ldmatrix k-half offset (u32)

    float acc[4][4][4];
#pragma unroll
    for (int mf = 0; mf < 4; mf++)
#pragma unroll
        for (int nf = 0; nf < 4; nf++)
#pragma unroll
            for (int j = 0; j < 4; j++) acc[mf][nf][j] = 0.f;

    const int arow = tid >> 1;
    const int aku  = (tid & 1) * 8;
    const int bk2 = tid >> 4;
    const int bn0 = (tid & 15) * 8;

    float4 av[4];
    uint4  ah[2];
    float4 bv[4];
    if (Ah) {
        ah[0] = *(const uint4*)&Ah[(size_t)(m0 + arow) * (K / 2) + aku];
        ah[1] = *(const uint4*)&Ah[(size_t)(m0 + arow) * (K / 2) + aku + 4];
    } else {
#pragma unroll
        for (int i = 0; i < 4; i++)
            av[i] = *(const float4*)&A[(size_t)(m0 + arow) * K + aku * 2 + i * 4];
    }
    bv[0] = *(const float4*)&Bw[(size_t)(2 * bk2)     * N + n0 + bn0];
    bv[1] = *(const float4*)&Bw[(size_t)(2 * bk2)     * N + n0 + bn0 + 4];
    bv[2] = *(const float4*)&Bw[(size_t)(2 * bk2 + 1) * N + n0 + bn0];
    bv[3] = *(const float4*)&Bw[(size_t)(2 * bk2 + 1) * N + n0 + bn0 + 4];

    int s = 0;
    for (int k0 = 0; k0 < K; k0 += 32) {
        unsigned* Ab = As + s * 128 * AST;
        unsigned* Bb = Bs + s * 16 * BST;
        if (Ah) {
            *(uint4*)&Ab[arow * AST + aku]     = ah[0];
            *(uint4*)&Ab[arow * AST + aku + 4] = ah[1];
        } else {
            uint4 u0 = {f2h2(av[0].x, av[0].y), f2h2(av[0].z, av[0].w),
                        f2h2(av[1].x, av[1].y), f2h2(av[1].z, av[1].w)};
            uint4 u1 = {f2h2(av[2].x, av[2].y), f2h2(av[2].z, av[2].w),
                        f2h2(av[3].x, av[3].y), f2h2(av[3].z, av[3].w)};
            *(uint4*)&Ab[arow * AST + aku]     = u0;
            *(uint4*)&Ab[arow * AST + aku + 4] = u1;
        }
        {
            uint4 u0 = {f2h2(bv[0].x, bv[2].x), f2h2(bv[0].y, bv[2].y),
                        f2h2(bv[0].z, bv[2].z), f2h2(bv[0].w, bv[2].w)};
            uint4 u1 = {f2h2(bv[1].x, bv[3].x), f2h2(bv[1].y, bv[3].y),
                        f2h2(bv[1].z, bv[3].z), f2h2(bv[1].w, bv[3].w)};
            *(uint4*)&Bb[bk2 * BST + bn0]     = u0;
            *(uint4*)&Bb[bk2 * BST + bn0 + 4] = u1;
        }
        __syncthreads();

        if (k0 + 32 < K) {
            if (Ah) {
                ah[0] = *(const uint4*)&Ah[(size_t)(m0 + arow) * (K / 2) + (k0 + 32) / 2 + aku];
                ah[1] = *(const uint4*)&Ah[(size_t)(m0 + arow) * (K / 2) + (k0 + 32) / 2 + aku + 4];
            } else {
#pragma unroll
                for (int i = 0; i < 4; i++)
                    av[i] = *(const float4*)&A[(size_t)(m0 + arow) * K + k0 + 32 + aku * 2 + i * 4];
            }
            bv[0] = *(const float4*)&Bw[(size_t)(k0 + 32 + 2 * bk2)     * N + n0 + bn0];
            bv[1] = *(const float4*)&Bw[(size_t)(k0 + 32 + 2 * bk2)     * N + n0 + bn0 + 4];
            bv[2] = *(const float4*)&Bw[(size_t)(k0 + 32 + 2 * bk2 + 1) * N + n0 + bn0];
            bv[3] = *(const float4*)&Bw[(size_t)(k0 + 32 + 2 * bk2 + 1) * N + n0 + bn0 + 4];
        }

        const uint32_t abase_s = as_base + 4u * (s * 128 * AST);
#pragma unroll
        for (int ks = 0; ks < 2; ks++) {
            const int kk = ks * 8 + c;
            unsigned a[4][4], b[4][2];
#pragma unroll
            for (int mf = 0; mf < 4; mf++)
                ldmx4(a[mf], abase_s +
                      4u * ((wm + mf * 16 + lm_row) * AST + ks * 8 + lm_k));
#pragma unroll
            for (int nf = 0; nf < 4; nf++) {
                int n = wn + nf * 8 + g;
                b[nf][0] = Bb[kk * BST + n];
                b[nf][1] = Bb[(kk + 4) * BST + n];
            }
#pragma unroll
            for (int mf = 0; mf < 4; mf++)
#pragma unroll
                for (int nf = 0; nf < 4; nf++)
                    mma_f16(acc[mf][nf], a[mf][0], a[mf][1], a[mf][2], a[mf][3],
                            b[nf][0], b[nf][1]);
        }
        s ^= 1;
    }

    if (mode == 1) {
#pragma unroll
        for (int mf = 0; mf < 4; mf++)
#pragma unroll
            for (int nf = 0; nf < 4; nf++) {
                int row  = m0 + wm + mf * 16 + g;
                int col2 = (n0 + wn + nf * 8) / 2 + c;
                Ch[(size_t)row * (N / 2) + col2] =
                    f2h2(acc[mf][nf][0] * oscale, acc[mf][nf][1] * oscale);
                Ch[(size_t)(row + 8) * (N / 2) + col2] =
                    f2h2(acc[mf][nf][2] * oscale, acc[mf][nf][3] * oscale);
            }
    } else if (mode == 2) {
        // V key-pair pack: rows r (g even) pair with r+1 (lane^4 holds it)
#pragma unroll
        for (int mf = 0; mf < 4; mf++)
#pragma unroll
            for (int nf = 0; nf < 4; nf++) {
                float p0 = __shfl_xor_sync(0xffffffffu, acc[mf][nf][0], 4);
                float p1 = __shfl_xor_sync(0xffffffffu, acc[mf][nf][1], 4);
                float p2 = __shfl_xor_sync(0xffffffffu, acc[mf][nf][2], 4);
                float p3 = __shfl_xor_sync(0xffffffffu, acc[mf][nf][3], 4);
                if (!(g & 1)) {
                    int r0  = m0 + wm + mf * 16 + g;         // even row
                    int col = n0 + wn + nf * 8 + 2 * c;
                    uint2 u0 = {f2h2(acc[mf][nf][0], p0), f2h2(acc[mf][nf][1], p1)};
                    *(uint2*)&g_Vp[(size_t)(r0 >> 1) * DK + col] = u0;
                    uint2 u1 = {f2h2(acc[mf][nf][2], p2), f2h2(acc[mf][nf][3], p3)};
                    *(uint2*)&g_Vp[(size_t)((r0 + 8) >> 1) * DK + col] = u1;
                }
            }
    } else {
#pragma unroll
        for (int mf = 0; mf < 4; mf++)
#pragma unroll
            for (int nf = 0; nf < 4; nf++) {
                size_t r0 = (size_t)(m0 + wm + mf * 16 + g) * N + n0 + wn + nf * 8 + 2 * c;
                float2 lo = {acc[mf][nf][0], acc[mf][nf][1]};
                float2 hi = {acc[mf][nf][2], acc[mf][nf][3]};
                *(float2*)&C[r0]                 = lo;
                *(float2*)&C[r0 + (size_t)8 * N] = hi;
            }
    }
}

__global__ __launch_bounds__(256) void qkv_kernel(
    const float* __restrict__ x, const float* __restrict__ Wq,
    const float* __restrict__ Wk, const float* __restrict__ Wv)
{
    const float scale = 0.08838834764831845f;   // 1/sqrt(128), folded into Q
    if (blockIdx.z == 0)
        gemm128_f16(x, nullptr, Wq, nullptr, g_Qh, scale, 1, DK, DD, blockIdx.x * 128, 0);
    else if (blockIdx.z == 1)
        gemm128_f16(x, nullptr, Wk, nullptr, g_Kh, 1.0f, 1, DK, DD, blockIdx.x * 128, 0);
    else
        gemm128_f16(x, nullptr, Wv, nullptr, nullptr, 1.0f, 2, DK, DD, blockIdx.x * 128, 0);
}

__global__ __launch_bounds__(256) void outproj_kernel(
    const float* __restrict__ Wo, float* __restrict__ out)
{
    gemm128_f16(nullptr, g_Oh, Wo, out, nullptr, 1.0f, 0, DD, DK,
                blockIdx.y * 128, blockIdx.x * 128);
}

// ---------------------------------------------------------------------------
// Flash attention, fp16 mma (m16n8k16), split-KV, cp.async staging.
// BQ=128, BKV=32, 256 threads = 8 warps (warp owns 16 q-rows), chunk = 8
// tiles -> 288 blocks = full wave at 2 blocks/SM. Double-buffered K/V,
// ONE barrier per tile; staging = 16B cp.async of pre-packed fp16.
// Q fragments via ldmatrix.x4. Partial O written as packed fp16.
// ---------------------------------------------------------------------------
#define QS2 68
#define KS2 68
#define VST 136
#define OFF_K (128*QS2)
#define OFF_V (OFF_K + 2*BKV*KS2)
#define FLASH_SMEM ((OFF_V + 2*16*VST) * 4)   // 69,632 bytes

__global__ __launch_bounds__(256, 2) void flash_kernel()
{
    extern __shared__ __align__(16) unsigned smf[];
    unsigned* Ks = smf + OFF_K;
    unsigned* Vs = smf + OFF_V;

    const int tid = threadIdx.x, lane = tid & 31, w = tid >> 5;
    const int g = lane >> 2, c = lane & 3;
    const int wm = w * 16;
    const uint32_t sbase = smem_u32(smf);
    // ldmatrix address for Q fragments (warp-row block wm)
    const uint32_t qs_lm = sbase +
        4u * ((wm + (lane & 15)) * QS2 + (lane >> 4) * 4);

    // ---- schedule decode: reversed order puts big (qt) chunks first ----
    const int b  = blockIdx.x / BPB;
    const int wr = BPB - 1 - (blockIdx.x % BPB);
    int qt = 0, chunk = 0, prefix = 0;
    {
        int accn = 0;
        for (int q = 0; q < 16; q++) {
            int n = (q + 2) >> 1;              // ceil((4q+4)/8)
            if (wr < accn + n) { qt = q; chunk = wr - accn; prefix = accn; break; }
            accn += n;
        }
    }
    const int slot = b * BPB + prefix + chunk;
    const int q0 = qt * 128;
    const int it_total = 4 * qt + 4;
    const int t0 = chunk * CHUNK;
    const int tlen = (it_total - t0 < CHUNK) ? (it_total - t0) : CHUNK;

    const size_t bT  = (size_t)b * TT;
    const size_t bT2 = (size_t)b * (TT / 2);

    // staging indices
    const int kr = tid >> 3,  kku = (tid & 7) * 8;    // K: row, u32 group
    const int vk2 = tid >> 4, vn0 = (tid & 15) * 8;   // V: key-pair, n group
    const int qr = tid >> 1,  qku = (tid & 1) * 32;   // Q: row, u32 group

    auto stage = [&](int t, int s) {
        uint32_t kb = sbase + (OFF_K + s * BKV * KS2 + kr * KS2 + kku) * 4;
        const unsigned* ksrc = &g_Kh[(bT + (size_t)t * BKV + kr) * 64 + kku];
        cp16(kb,      ksrc);
        cp16(kb + 16, ksrc + 4);
        uint32_t vb = sbase + (OFF_V + s * 16 * VST + vk2 * VST + vn0) * 4;
        const unsigned* vsrc = &g_Vp[(bT2 + (size_t)t * 16 + vk2) * DK + vn0];
        cp16(vb,      vsrc);
        cp16(vb + 16, vsrc + 4);
    };

    // preload Q + first KV tile
    {
        const unsigned* qsrc = &g_Qh[(bT + q0 + qr) * 64 + qku];
        uint32_t qb = sbase + (qr * QS2 + qku) * 4;
#pragma unroll
        for (int i = 0; i < 8; i++)
            cp16(qb + i * 16, qsrc + i * 4);
        stage(t0, 0);
        CP_COMMIT();
        CP_WAIT0();
        __syncthreads();
    }

    float mr0 = -1e30f, mr1 = -1e30f, l0 = 0.f, l1 = 0.f;
    float O[16][4];
#pragma unroll
    for (int nf = 0; nf < 16; nf++)
#pragma unroll
        for (int j = 0; j < 4; j++) O[nf][j] = 0.f;

    int s = 0;
    for (int ti = 0; ti < tlen; ti++) {
        const int t = t0 + ti;
        unsigned* Kb = Ks + s * BKV * KS2;
        unsigned* Vb = Vs + s * 16 * VST;

        // stage next tile (cp.async overlaps all compute below)
        if (ti + 1 < tlen) { stage(t + 1, s ^ 1); CP_COMMIT(); }

        // --- S = Q K^T : warp 16x32, 4 n-frags, 8 k16-slices ---
        float sfr[4][4];
#pragma unroll
        for (int nf = 0; nf < 4; nf++)
#pragma unroll
            for (int j = 0; j < 4; j++) sfr[nf][j] = 0.f;

#pragma unroll
        for (int ks = 0; ks < 8; ks++) {
            const int kk = ks * 8 + c;
            unsigned aq[4];
            ldmx4(aq, qs_lm + ks * 32);
#pragma unroll
            for (int nf = 0; nf < 4; nf++) {
                int n = nf * 8 + g;
                mma_f16(sfr[nf], aq[0], aq[1], aq[2], aq[3],
                        Kb[n * KS2 + kk], Kb[n * KS2 + kk + 4]);
            }
        }

        // causal mask (scale pre-folded into Q)
        if (t * BKV + BKV - 1 > q0 + wm) {
            const int r0g = q0 + wm + g, r1g = r0g + 8;
#pragma unroll
            for (int nf = 0; nf < 4; nf++) {
                int col = t * BKV + nf * 8 + 2 * c;
                if (col     > r0g) sfr[nf][0] = -1e30f;
                if (col + 1 > r0g) sfr[nf][1] = -1e30f;
                if (col     > r1g) sfr[nf][2] = -1e30f;
                if (col + 1 > r1g) sfr[nf][3] = -1e30f;
            }
        }

        // --- online softmax (rows wm+g, wm+g+8; reduce over 4-lane quad) ---
        float rm0 = -1e30f, rm1 = -1e30f;
#pragma unroll
        for (int nf = 0; nf < 4; nf++) {
            rm0 = fmaxf(rm0, fmaxf(sfr[nf][0], sfr[nf][1]));
            rm1 = fmaxf(rm1, fmaxf(sfr[nf][2], sfr[nf][3]));
        }
        rm0 = fmaxf(rm0, __shfl_xor_sync(0xffffffffu, rm0, 1));
        rm0 = fmaxf(rm0, __shfl_xor_sync(0xffffffffu, rm0, 2));
        rm1 = fmaxf(rm1, __shfl_xor_sync(0xffffffffu, rm1, 1));
        rm1 = fmaxf(rm1, __shfl_xor_sync(0xffffffffu, rm1, 2));

        float mn0 = fmaxf(mr0, rm0), mn1 = fmaxf(mr1, rm1);
        float al0 = __expf(mr0 - mn0), al1 = __expf(mr1 - mn1);
        float sum0 = 0.f, sum1 = 0.f;
#pragma unroll
        for (int nf = 0; nf < 4; nf++) {
            sfr[nf][0] = __expf(sfr[nf][0] - mn0);
            sfr[nf][1] = __expf(sfr[nf][1] - mn0);
            sfr[nf][2] = __expf(sfr[nf][2] - mn1);
            sfr[nf][3] = __expf(sfr[nf][3] - mn1);
            sum0 += sfr[nf][0] + sfr[nf][1];
            sum1 += sfr[nf][2] + sfr[nf][3];
        }
        sum0 += __shfl_xor_sync(0xffffffffu, sum0, 1);
        sum0 += __shfl_xor_sync(0xffffffffu, sum0, 2);
        sum1 += __shfl_xor_sync(0xffffffffu, sum1, 1);
        sum1 += __shfl_xor_sync(0xffffffffu, sum1, 2);

        l0 = l0 * al0 + sum0; l1 = l1 * al1 + sum1;
        mr0 = mn0; mr1 = mn1;
#pragma unroll
        for (int nf = 0; nf < 16; nf++) {
            O[nf][0] *= al0; O[nf][1] *= al0;
            O[nf][2] *= al1; O[nf][3] *= al1;
        }

        // --- O += P V : S-frags pack directly into PV A-frags ---
#pragma unroll
        for (int ksl = 0; ksl < 2; ksl++) {
            unsigned a0 = f2h2(sfr[2 * ksl][0],     sfr[2 * ksl][1]);
            unsigned a1 = f2h2(sfr[2 * ksl][2],     sfr[2 * ksl][3]);
            unsigned a2 = f2h2(sfr[2 * ksl + 1][0], sfr[2 * ksl + 1][1]);
            unsigned a3 = f2h2(sfr[2 * ksl + 1][2], sfr[2 * ksl + 1][3]);
            const int kk = ksl * 8 + c;
#pragma unroll
            for (int nf = 0; nf < 16; nf++) {
                int n = nf * 8 + g;
                mma_f16(O[nf], a0, a1, a2, a3,
                        Vb[kk * VST + n], Vb[(kk + 4) * VST + n]);
            }
        }

        if (ti + 1 < tlen) CP_WAIT0();
        __syncthreads();
        s ^= 1;
    }

    // ---- write partial (unnormalized O as packed fp16, plus m, l) ----
    unsigned* pO = g_pOh + (size_t)slot * 128 * 64;
#pragma unroll
    for (int nf = 0; nf < 16; nf++) {
        int col2 = nf * 4 + c;
        pO[(wm + g) * 64 + col2]     = f2h2(O[nf][0], O[nf][1]);
        pO[(wm + g + 8) * 64 + col2] = f2h2(O[nf][2], O[nf][3]);
    }
    if (c == 0) {
        float* ml = g_pml + slot * 256;
        ml[(wm + g) * 2]         = mr0;
        ml[(wm + g) * 2 + 1]     = l0;
        ml[(wm + g + 8) * 2]     = mr1;
        ml[(wm + g + 8) * 2 + 1] = l1;
    }
}

// ---------------------------------------------------------------------------
// Combine partial chunks -> g_Oh (normalized, packed fp16).
// One thread per (b, qt, row, 4 cols): 262144 threads, 1024 blocks.
// ---------------------------------------------------------------------------
__global__ __launch_bounds__(256) void combine_kernel()
{
    const int idx  = blockIdx.x * 256 + threadIdx.x;
    const int col2 = (idx & 31) * 2;       // u32 (half2) index, 2 per thread
    const int row  = (idx >> 5) & 127;
    const int bqt  = idx >> 12;            // 0..63
    const int b = bqt >> 4, qt = bqt & 15;
    const int nch = (qt + 2) >> 1;         // ceil((4qt+4)/8)
    int prefix = 0;
#pragma unroll
    for (int q = 0; q < 16; q++)
        if (q < qt) prefix += (q + 2) >> 1;
    const int base = b * BPB + prefix;

    // pass 1: global max m
    float M = -1e30f;
    for (int i = 0; i < nch; i++)
        M = fmaxf(M, g_pml[(base + i) * 256 + row * 2]);

    // pass 2: weighted accumulate
    float L = 0.f;
    float4 a = {0.f, 0.f, 0.f, 0.f};
    for (int i = 0; i < nch; i++) {
        float mi = g_pml[(base + i) * 256 + row * 2];
        float li = g_pml[(base + i) * 256 + row * 2 + 1];
        float wgt = __expf(mi - M);
        L += wgt * li;
        uint2 v = *(const uint2*)&g_pOh[((size_t)(base + i) * 128 + row) * 64 + col2];
        float2 lo = h2f2(v.x), hi = h2f2(v.y);
        a.x += wgt * lo.x; a.y += wgt * lo.y;
        a.z += wgt * hi.x; a.w += wgt * hi.y;
    }
    const float invL = 1.f / L;
    const size_t orow = (size_t)b * TT + qt * 128 + row;
    g_Oh[orow * 64 + col2]     = f2h2(a.x * invL, a.y * invL);
    g_Oh[orow * 64 + col2 + 1] = f2h2(a.z * invL, a.w * invL);
}

// ---------------------------------------------------------------------------
extern "C" void kernel_launch(void* const* d_in, const int* in_sizes, int n_in,
                              void* d_out, int out_size)
{
    const float* x  = (const float*)d_in[0];
    const float* Wq = (const float*)d_in[1];
    const float* Wk = (const float*)d_in[2];
    const float* Wv = (const float*)d_in[3];
    const float* Wo = (const float*)d_in[4];
    float* out = (float*)d_out;

    cudaFuncSetAttribute(flash_kernel,
                         cudaFuncAttributeMaxDynamicSharedMemorySize, FLASH_SMEM);

    // QKV projections (fp16 mma): Q/K packed fp16, V key-pair packed fp16
    qkv_kernel<<<dim3(RR / 128, 1, 3), 256>>>(x, Wq, Wk, Wv);

    // Split-KV causal flash attention (288 blocks = full wave at 2/SM)
    flash_kernel<<<NSLOT, 256, FLASH_SMEM>>>();

    // Merge partial softmax chunks -> packed fp16 O (1024 blocks)
    combine_kernel<<<RR * 32 / 256, 256>>>();

    // Output projection: [8192,128] @ [128,1024], A pre-packed fp16
    outproj_kernel<<<dim3(DD / 128, RR / 128), 256>>>(Wo, out);
}

// round 14
// speedup vs baseline: 1.9907x; 1.0196x over previous
#include <cuda_runtime.h>
#include <cuda_fp16.h>
#include <math.h>
#include <stdint.h>

#define BB 4
#define TT 2048
#define DD 1024
#define DK 128
#define RR (BB*TT)   // 8192

#define BKV 32
#define CHUNK 8             // KV tiles per flash block
#define BPB 72              // flash blocks per batch: sum_{q=0..15} ceil((4q+4)/8)
#define NSLOT (BB*BPB)      // 288 partial slots

// Scratch (device globals: allocation-free)
__device__ unsigned g_Qh[RR*(DK/2)];            // Q fp16 packed half2, pre-scaled
__device__ unsigned g_Kh[RR*(DK/2)];            // K fp16 packed half2
__device__ unsigned g_Vp[(RR/2)*DK];            // V fp16, key-pair packed: [t2][d]
__device__ unsigned g_Oh[RR*(DK/2)];            // attention O, fp16 packed half2
__device__ unsigned g_pOh[(size_t)NSLOT*128*(DK/2)]; // partial O, fp16 packed
__device__ float    g_pml[NSLOT*128*2];         // partial (m,l) per row
__device__ unsigned g_Wh[3*512*128];            // Wq/Wk/Wv packed k-pair: [k2][n]
__device__ unsigned g_WoH[64*1024];             // Wo packed k-pair: [k2][n]

// pack two f32 -> half2 u32 (lo = first arg, hi = second arg)
__device__ __forceinline__ unsigned f2h2(float lo, float hi) {
    unsigned u;
    asm("cvt.rn.f16x2.f32 %0, %1, %2;" : "=r"(u) : "f"(hi), "f"(lo));
    return u;
}

__device__ __forceinline__ float2 h2f2(unsigned u) {
    __half2 h = *(__half2*)&u;
    return __half22float2(h);
}

__device__ __forceinline__ void mma_f16(float c[4],
    unsigned a0, unsigned a1, unsigned a2, unsigned a3,
    unsigned b0, unsigned b1)
{
    asm volatile(
        "mma.sync.aligned.m16n8k16.row.col.f32.f16.f16.f32 "
        "{%0,%1,%2,%3}, {%4,%5,%6,%7}, {%8,%9}, {%0,%1,%2,%3};"
        : "+f"(c[0]), "+f"(c[1]), "+f"(c[2]), "+f"(c[3])
        : "r"(a0), "r"(a1), "r"(a2), "r"(a3), "r"(b0), "r"(b1));
}

__device__ __forceinline__ void ldmx4(unsigned* r, uint32_t addr) {
    asm volatile("ldmatrix.sync.aligned.m8n8.x4.shared.b16 {%0,%1,%2,%3}, [%4];"
        : "=r"(r[0]), "=r"(r[1]), "=r"(r[2]), "=r"(r[3]) : "r"(addr));
}

__device__ __forceinline__ uint32_t smem_u32(const void* p) {
    uint32_t a;
    asm("{ .reg .u64 t; cvta.to.shared.u64 t, %1; cvt.u32.u64 %0, t; }"
        : "=r"(a) : "l"(p));
    return a;
}

__device__ __forceinline__ void cp16(uint32_t dst, const void* src) {
    asm volatile("cp.async.ca.shared.global [%0], [%1], 16;"
                 :: "r"(dst), "l"(src) : "memory");
}
#define CP_COMMIT() asm volatile("cp.async.commit_group;" ::: "memory")
#define CP_WAIT0()  asm volatile("cp.async.wait_group 0;"  ::: "memory")

// ---------------------------------------------------------------------------
// Pack weights into fp16 k-pair layouts (matches GEMM B smem layout):
// g_Wh[w][k2*128+n] = half2(W[2k2][n], W[2k2+1][n]) for Wq/Wk/Wv (K=1024,N=128)
// g_WoH[k2*1024+n]  = same for Wo (K=128, N=1024).  Grid: 1024 x 256.
// ---------------------------------------------------------------------------
__global__ __launch_bounds__(256) void packw_kernel(
    const float* __restrict__ Wq, const float* __restrict__ Wk,
    const float* __restrict__ Wv, const float* __restrict__ Wo)
{
    const int idx = blockIdx.x * 256 + threadIdx.x;
    if (idx < 3 * 65536) {
        const int wsel = idx >> 16;
        const int r = idx & 65535;
        const int k2 = r >> 7, n = r & 127;
        const float* W = (wsel == 0) ? Wq : (wsel == 1) ? Wk : Wv;
        g_Wh[idx] = f2h2(W[(2 * k2) * 128 + n], W[(2 * k2 + 1) * 128 + n]);
    } else {
        const int r = idx - 3 * 65536;
        const int k2 = r >> 10, n = r & 1023;
        g_WoH[r] = f2h2(Wo[(2 * k2) * 1024 + n], Wo[(2 * k2 + 1) * 1024 + n]);
    }
}

// ---------------------------------------------------------------------------
// QKV GEMM: C[128x128 tile] = x[M,1024] @ W[1024,128]. A = fp32 x (cvt at
// staging, register prefetch); B = pre-packed fp16 weights via cp.async.
// mode: 1 = half2 Ch out (oscale folded), 2 = V key-pair packed out to g_Vp.
// 256 threads = 8 warps as 2(m) x 4(n); warp tile 64x32; BK=32.
// As: [m][k2] packed half2, stride 20 u32 (ldmatrix). Bs: [k2][n] stride 136.
// ---------------------------------------------------------------------------
#define AST 20
#define BST 136

__device__ __forceinline__ void qkv_gemm(
    const float* __restrict__ A, const unsigned* __restrict__ Bh,
    unsigned* __restrict__ Ch, float oscale, int mode, int m0)
{
    __shared__ __align__(16) unsigned As[2 * 128 * AST];
    __shared__ __align__(16) unsigned Bs[2 * 16 * BST];

    const int tid = threadIdx.x, lane = tid & 31, w = tid >> 5;
    const int wm = (w >> 2) * 64, wn = (w & 3) * 32;
    const int g = lane >> 2, c = lane & 3;
    const uint32_t as_base = smem_u32(As);
    const uint32_t bs_base = smem_u32(Bs);

    float acc[4][4][4];
#pragma unroll
    for (int mf = 0; mf < 4; mf++)
#pragma unroll
        for (int nf = 0; nf < 4; nf++)
#pragma unroll
            for (int j = 0; j < 4; j++) acc[mf][nf][j] = 0.f;

    const int arow = tid >> 1;
    const int aku  = (tid & 1) * 8;
    const int bk2  = tid >> 4;            // 0..15
    const int bn0  = (tid & 15) * 8;

    // B slab cp.async issue (slab at k0)
    auto stageB = [&](int k0, int s) {
        uint32_t dst = bs_base + 4u * (s * 16 * BST + bk2 * BST + bn0);
        const unsigned* src = &Bh[(k0 / 2 + bk2) * 128 + bn0];
        cp16(dst, src);
        cp16(dst + 16, src + 4);
    };

    // prologue: B slab0 async; A slab0 regs
    stageB(0, 0);
    CP_COMMIT();
    float4 av[4];
#pragma unroll
    for (int i = 0; i < 4; i++)
        av[i] = *(const float4*)&A[(size_t)(m0 + arow) * DD + aku * 2 + i * 4];

    int s = 0;
    for (int k0 = 0; k0 < DD; k0 += 32) {
        unsigned* Ab = As + s * 128 * AST;
        {
            uint4 u0 = {f2h2(av[0].x, av[0].y), f2h2(av[0].z, av[0].w),
                        f2h2(av[1].x, av[1].y), f2h2(av[1].z, av[1].w)};
            uint4 u1 = {f2h2(av[2].x, av[2].y), f2h2(av[2].z, av[2].w),
                        f2h2(av[3].x, av[3].y), f2h2(av[3].z, av[3].w)};
            *(uint4*)&Ab[arow * AST + aku]     = u0;
            *(uint4*)&Ab[arow * AST + aku + 4] = u1;
        }
        CP_WAIT0();
        __syncthreads();

        if (k0 + 32 < DD) {
#pragma unroll
            for (int i = 0; i < 4; i++)
                av[i] = *(const float4*)&A[(size_t)(m0 + arow) * DD + k0 + 32 + aku * 2 + i * 4];
            stageB(k0 + 32, s ^ 1);
            CP_COMMIT();
        }

        unsigned* Bb = Bs + s * 16 * BST;
        const uint32_t abase_s = as_base + 4u * (s * 128 * AST);
#pragma unroll
        for (int ks = 0; ks < 2; ks++) {
            const int kk = ks * 8 + c;
            unsigned a[4][4], b[4][2];
#pragma unroll
            for (int mf = 0; mf < 4; mf++)
                ldmx4(a[mf], abase_s +
                      4u * ((wm + mf * 16 + (lane & 15)) * AST + ks * 8 + (lane >> 4) * 4));
#pragma unroll
            for (int nf = 0; nf < 4; nf++) {
                int n = wn + nf * 8 + g;
                b[nf][0] = Bb[kk * BST + n];
                b[nf][1] = Bb[(kk + 4) * BST + n];
            }
#pragma unroll
            for (int mf = 0; mf < 4; mf++)
#pragma unroll
                for (int nf = 0; nf < 4; nf++)
                    mma_f16(acc[mf][nf], a[mf][0], a[mf][1], a[mf][2], a[mf][3],
                            b[nf][0], b[nf][1]);
        }
        s ^= 1;
    }

    if (mode == 1) {
#pragma unroll
        for (int mf = 0; mf < 4; mf++)
#pragma unroll
            for (int nf = 0; nf < 4; nf++) {
                int row  = m0 + wm + mf * 16 + g;
                int col2 = (wn + nf * 8) / 2 + c;
                Ch[(size_t)row * 64 + col2] =
                    f2h2(acc[mf][nf][0] * oscale, acc[mf][nf][1] * oscale);
                Ch[(size_t)(row + 8) * 64 + col2] =
                    f2h2(acc[mf][nf][2] * oscale, acc[mf][nf][3] * oscale);
            }
    } else {
        // V key-pair pack: rows r (g even) pair with r+1 (lane^4 holds it)
#pragma unroll
        for (int mf = 0; mf < 4; mf++)
#pragma unroll
            for (int nf = 0; nf < 4; nf++) {
                float p0 = __shfl_xor_sync(0xffffffffu, acc[mf][nf][0], 4);
                float p1 = __shfl_xor_sync(0xffffffffu, acc[mf][nf][1], 4);
                float p2 = __shfl_xor_sync(0xffffffffu, acc[mf][nf][2], 4);
                float p3 = __shfl_xor_sync(0xffffffffu, acc[mf][nf][3], 4);
                if (!(g & 1)) {
                    int r0  = m0 + wm + mf * 16 + g;
                    int col = wn + nf * 8 + 2 * c;
                    uint2 u0 = {f2h2(acc[mf][nf][0], p0), f2h2(acc[mf][nf][1], p1)};
                    *(uint2*)&g_Vp[(size_t)(r0 >> 1) * DK + col] = u0;
                    uint2 u1 = {f2h2(acc[mf][nf][2], p2), f2h2(acc[mf][nf][3], p3)};
                    *(uint2*)&g_Vp[(size_t)((r0 + 8) >> 1) * DK + col] = u1;
                }
            }
    }
}

__global__ __launch_bounds__(256) void qkv_kernel(const float* __restrict__ x)
{
    const float scale = 0.08838834764831845f;   // 1/sqrt(128), folded into Q
    const unsigned* Bh = g_Wh + blockIdx.z * 65536;
    if (blockIdx.z == 0)
        qkv_gemm(x, Bh, g_Qh, scale, 1, blockIdx.x * 128);
    else if (blockIdx.z == 1)
        qkv_gemm(x, Bh, g_Kh, 1.0f, 1, blockIdx.x * 128);
    else
        qkv_gemm(x, Bh, nullptr, 1.0f, 2, blockIdx.x * 128);
}

// ---------------------------------------------------------------------------
// Output projection: out[128x128 tile] = O[8192,128] @ Wo[128,1024].
// K=128 fits entirely in smem: one-shot cp.async stage (A fp16 g_Oh, B packed
// g_WoH), ONE barrier, then 8 uninterrupted k16-slices. 68 KB smem -> 2/SM.
// ---------------------------------------------------------------------------
#define OA_ST 68
#define OB_ST 136
#define OP_SMEM ((128*OA_ST + 64*OB_ST) * 4)   // 69,632 bytes

__global__ __launch_bounds__(256) void outproj_kernel(float* __restrict__ out)
{
    extern __shared__ __align__(16) unsigned sop[];
    unsigned* Bsm = sop + 128 * OA_ST;

    const int tid = threadIdx.x, lane = tid & 31, w = tid >> 5;
    const int wm = (w >> 2) * 64, wn = (w & 3) * 32;
    const int g = lane >> 2, c = lane & 3;
    const int m0 = blockIdx.y * 128, n0 = blockIdx.x * 128;
    const uint32_t sb = smem_u32(sop);

    // stage A: 128 rows x 64 u32 (8 cp16 per thread)
    {
        const int row = tid >> 1, half = tid & 1;
        const unsigned* src = &g_Oh[(size_t)(m0 + row) * 64 + half * 32];
        uint32_t dst = sb + 4u * (row * OA_ST + half * 32);
#pragma unroll
        for (int i = 0; i < 8; i++)
            cp16(dst + i * 16, src + i * 4);
    }
    // stage B: 64 k2-rows x 128 u32 (8 cp16 per thread)
    {
        const int bn = (tid & 15) * 8;
#pragma unroll
        for (int it = 0; it < 4; it++) {
            const int k2 = (tid >> 4) + it * 16;
            const unsigned* src = &g_WoH[k2 * 1024 + n0 + bn];
            uint32_t dst = sb + 4u * (128 * OA_ST + k2 * OB_ST + bn);
            cp16(dst, src);
            cp16(dst + 16, src + 4);
        }
    }
    CP_COMMIT();
    CP_WAIT0();
    __syncthreads();

    float acc[4][4][4];
#pragma unroll
    for (int mf = 0; mf < 4; mf++)
#pragma unroll
        for (int nf = 0; nf < 4; nf++)
#pragma unroll
            for (int j = 0; j < 4; j++) acc[mf][nf][j] = 0.f;

    const uint32_t a_lm = sb + 4u * ((wm + (lane & 15)) * OA_ST + (lane >> 4) * 4);
#pragma unroll
    for (int ks = 0; ks < 8; ks++) {
        const int kk = ks * 8 + c;
        unsigned a[4][4], b[4][2];
#pragma unroll
        for (int mf = 0; mf < 4; mf++)
            ldmx4(a[mf], a_lm + 4u * (mf * 16 * OA_ST) + ks * 32);
#pragma unroll
        for (int nf = 0; nf < 4; nf++) {
            int n = wn + nf * 8 + g;
            b[nf][0] = Bsm[kk * OB_ST + n];
            b[nf][1] = Bsm[(kk + 4) * OB_ST + n];
        }
#pragma unroll
        for (int mf = 0; mf < 4; mf++)
#pragma unroll
            for (int nf = 0; nf < 4; nf++)
                mma_f16(acc[mf][nf], a[mf][0], a[mf][1], a[mf][2], a[mf][3],
                        b[nf][0], b[nf][1]);
    }

#pragma unroll
    for (int mf = 0; mf < 4; mf++)
#pragma unroll
        for (int nf = 0; nf < 4; nf++) {
            size_t r0 = (size_t)(m0 + wm + mf * 16 + g) * DD + n0 + wn + nf * 8 + 2 * c;
            float2 lo = {acc[mf][nf][0], acc[mf][nf][1]};
            float2 hi = {acc[mf][nf][2], acc[mf][nf][3]};
            *(float2*)&out[r0]                  = lo;
            *(float2*)&out[r0 + (size_t)8 * DD] = hi;
        }
}

// ---------------------------------------------------------------------------
// Flash attention, fp16 mma (m16n8k16), split-KV, cp.async staging.
// (unchanged from R13 passing version)
// ---------------------------------------------------------------------------
#define QS2 68
#define KS2 68
#define VST 136
#define OFF_K (128*QS2)
#define OFF_V (OFF_K + 2*BKV*KS2)
#define FLASH_SMEM ((OFF_V + 2*16*VST) * 4)   // 69,632 bytes

__global__ __launch_bounds__(256, 2) void flash_kernel()
{
    extern __shared__ __align__(16) unsigned smf[];
    unsigned* Ks = smf + OFF_K;
    unsigned* Vs = smf + OFF_V;

    const int tid = threadIdx.x, lane = tid & 31, w = tid >> 5;
    const int g = lane >> 2, c = lane & 3;
    const int wm = w * 16;
    const uint32_t sbase = smem_u32(smf);
    const uint32_t qs_lm = sbase +
        4u * ((wm + (lane & 15)) * QS2 + (lane >> 4) * 4);

    const int b  = blockIdx.x / BPB;
    const int wr = BPB - 1 - (blockIdx.x % BPB);
    int qt = 0, chunk = 0, prefix = 0;
    {
        int accn = 0;
        for (int q = 0; q < 16; q++) {
            int n = (q + 2) >> 1;
            if (wr < accn + n) { qt = q; chunk = wr - accn; prefix = accn; break; }
            accn += n;
        }
    }
    const int slot = b * BPB + prefix + chunk;
    const int q0 = qt * 128;
    const int it_total = 4 * qt + 4;
    const int t0 = chunk * CHUNK;
    const int tlen = (it_total - t0 < CHUNK) ? (it_total - t0) : CHUNK;

    const size_t bT  = (size_t)b * TT;
    const size_t bT2 = (size_t)b * (TT / 2);

    const int kr = tid >> 3,  kku = (tid & 7) * 8;
    const int vk2 = tid >> 4, vn0 = (tid & 15) * 8;
    const int qr = tid >> 1,  qku = (tid & 1) * 32;

    auto stage = [&](int t, int s) {
        uint32_t kb = sbase + (OFF_K + s * BKV * KS2 + kr * KS2 + kku) * 4;
        const unsigned* ksrc = &g_Kh[(bT + (size_t)t * BKV + kr) * 64 + kku];
        cp16(kb,      ksrc);
        cp16(kb + 16, ksrc + 4);
        uint32_t vb = sbase + (OFF_V + s * 16 * VST + vk2 * VST + vn0) * 4;
        const unsigned* vsrc = &g_Vp[(bT2 + (size_t)t * 16 + vk2) * DK + vn0];
        cp16(vb,      vsrc);
        cp16(vb + 16, vsrc + 4);
    };

    {
        const unsigned* qsrc = &g_Qh[(bT + q0 + qr) * 64 + qku];
        uint32_t qb = sbase + (qr * QS2 + qku) * 4;
#pragma unroll
        for (int i = 0; i < 8; i++)
            cp16(qb + i * 16, qsrc + i * 4);
        stage(t0, 0);
        CP_COMMIT();
        CP_WAIT0();
        __syncthreads();
    }

    float mr0 = -1e30f, mr1 = -1e30f, l0 = 0.f, l1 = 0.f;
    float O[16][4];
#pragma unroll
    for (int nf = 0; nf < 16; nf++)
#pragma unroll
        for (int j = 0; j < 4; j++) O[nf][j] = 0.f;

    int s = 0;
    for (int ti = 0; ti < tlen; ti++) {
        const int t = t0 + ti;
        unsigned* Kb = Ks + s * BKV * KS2;
        unsigned* Vb = Vs + s * 16 * VST;

        if (ti + 1 < tlen) { stage(t + 1, s ^ 1); CP_COMMIT(); }

        float sfr[4][4];
#pragma unroll
        for (int nf = 0; nf < 4; nf++)
#pragma unroll
            for (int j = 0; j < 4; j++) sfr[nf][j] = 0.f;

#pragma unroll
        for (int ks = 0; ks < 8; ks++) {
            const int kk = ks * 8 + c;
            unsigned aq[4];
            ldmx4(aq, qs_lm + ks * 32);
#pragma unroll
            for (int nf = 0; nf < 4; nf++) {
                int n = nf * 8 + g;
                mma_f16(sfr[nf], aq[0], aq[1], aq[2], aq[3],
                        Kb[n * KS2 + kk], Kb[n * KS2 + kk + 4]);
            }
        }

        if (t * BKV + BKV - 1 > q0 + wm) {
            const int r0g = q0 + wm + g, r1g = r0g + 8;
#pragma unroll
            for (int nf = 0; nf < 4; nf++) {
                int col = t * BKV + nf * 8 + 2 * c;
                if (col     > r0g) sfr[nf][0] = -1e30f;
                if (col + 1 > r0g) sfr[nf][1] = -1e30f;
                if (col     > r1g) sfr[nf][2] = -1e30f;
                if (col + 1 > r1g) sfr[nf][3] = -1e30f;
            }
        }

        float rm0 = -1e30f, rm1 = -1e30f;
#pragma unroll
        for (int nf = 0; nf < 4; nf++) {
            rm0 = fmaxf(rm0, fmaxf(sfr[nf][0], sfr[nf][1]));
            rm1 = fmaxf(rm1, fmaxf(sfr[nf][2], sfr[nf][3]));
        }
        rm0 = fmaxf(rm0, __shfl_xor_sync(0xffffffffu, rm0, 1));
        rm0 = fmaxf(rm0, __shfl_xor_sync(0xffffffffu, rm0, 2));
        rm1 = fmaxf(rm1, __shfl_xor_sync(0xffffffffu, rm1, 1));
        rm1 = fmaxf(rm1, __shfl_xor_sync(0xffffffffu, rm1, 2));

        float mn0 = fmaxf(mr0, rm0), mn1 = fmaxf(mr1, rm1);
        float al0 = __expf(mr0 - mn0), al1 = __expf(mr1 - mn1);
        float sum0 = 0.f, sum1 = 0.f;
#pragma unroll
        for (int nf = 0; nf < 4; nf++) {
            sfr[nf][0] = __expf(sfr[nf][0] - mn0);
            sfr[nf][1] = __expf(sfr[nf][1] - mn0);
            sfr[nf][2] = __expf(sfr[nf][2] - mn1);
            sfr[nf][3] = __expf(sfr[nf][3] - mn1);
            sum0 += sfr[nf][0] + sfr[nf][1];
            sum1 += sfr[nf][2] + sfr[nf][3];
        }
        sum0 += __shfl_xor_sync(0xffffffffu, sum0, 1);
        sum0 += __shfl_xor_sync(0xffffffffu, sum0, 2);
        sum1 += __shfl_xor_sync(0xffffffffu, sum1, 1);
        sum1 += __shfl_xor_sync(0xffffffffu, sum1, 2);

        l0 = l0 * al0 + sum0; l1 = l1 * al1 + sum1;
        mr0 = mn0; mr1 = mn1;
#pragma unroll
        for (int nf = 0; nf < 16; nf++) {
            O[nf][0] *= al0; O[nf][1] *= al0;
            O[nf][2] *= al1; O[nf][3] *= al1;
        }

#pragma unroll
        for (int ksl = 0; ksl < 2; ksl++) {
            unsigned a0 = f2h2(sfr[2 * ksl][0],     sfr[2 * ksl][1]);
            unsigned a1 = f2h2(sfr[2 * ksl][2],     sfr[2 * ksl][3]);
            unsigned a2 = f2h2(sfr[2 * ksl + 1][0], sfr[2 * ksl + 1][1]);
            unsigned a3 = f2h2(sfr[2 * ksl + 1][2], sfr[2 * ksl + 1][3]);
            const int kk = ksl * 8 + c;
#pragma unroll
            for (int nf = 0; nf < 16; nf++) {
                int n = nf * 8 + g;
                mma_f16(O[nf], a0, a1, a2, a3,
                        Vb[kk * VST + n], Vb[(kk + 4) * VST + n]);
            }
        }

        if (ti + 1 < tlen) CP_WAIT0();
        __syncthreads();
        s ^= 1;
    }

    unsigned* pO = g_pOh + (size_t)slot * 128 * 64;
#pragma unroll
    for (int nf = 0; nf < 16; nf++) {
        int col2 = nf * 4 + c;
        pO[(wm + g) * 64 + col2]     = f2h2(O[nf][0], O[nf][1]);
        pO[(wm + g + 8) * 64 + col2] = f2h2(O[nf][2], O[nf][3]);
    }
    if (c == 0) {
        float* ml = g_pml + slot * 256;
        ml[(wm + g) * 2]         = mr0;
        ml[(wm + g) * 2 + 1]     = l0;
        ml[(wm + g + 8) * 2]     = mr1;
        ml[(wm + g + 8) * 2 + 1] = l1;
    }
}

// ---------------------------------------------------------------------------
// Combine partial chunks -> g_Oh (normalized, packed fp16). 1024 blocks.
// ---------------------------------------------------------------------------
__global__ __launch_bounds__(256) void combine_kernel()
{
    const int idx  = blockIdx.x * 256 + threadIdx.x;
    const int col2 = (idx & 31) * 2;
    const int row  = (idx >> 5) & 127;
    const int bqt  = idx >> 12;
    const int b = bqt >> 4, qt = bqt & 15;
    const int nch = (qt + 2) >> 1;
    int prefix = 0;
#pragma unroll
    for (int q = 0; q < 16; q++)
        if (q < qt) prefix += (q + 2) >> 1;
    const int base = b * BPB + prefix;

    float M = -1e30f;
    for (int i = 0; i < nch; i++)
        M = fmaxf(M, g_pml[(base + i) * 256 + row * 2]);

    float L = 0.f;
    float4 a = {0.f, 0.f, 0.f, 0.f};
    for (int i = 0; i < nch; i++) {
        float mi = g_pml[(base + i) * 256 + row * 2];
        float li = g_pml[(base + i) * 256 + row * 2 + 1];
        float wgt = __expf(mi - M);
        L += wgt * li;
        uint2 v = *(const uint2*)&g_pOh[((size_t)(base + i) * 128 + row) * 64 + col2];
        float2 lo = h2f2(v.x), hi = h2f2(v.y);
        a.x += wgt * lo.x; a.y += wgt * lo.y;
        a.z += wgt * hi.x; a.w += wgt * hi.y;
    }
    const float invL = 1.f / L;
    const size_t orow = (size_t)b * TT + qt * 128 + row;
    g_Oh[orow * 64 + col2]     = f2h2(a.x * invL, a.y * invL);
    g_Oh[orow * 64 + col2 + 1] = f2h2(a.z * invL, a.w * invL);
}

// ---------------------------------------------------------------------------
extern "C" void kernel_launch(void* const* d_in, const int* in_sizes, int n_in,
                              void* d_out, int out_size)
{
    const float* x  = (const float*)d_in[0];
    const float* Wq = (const float*)d_in[1];
    const float* Wk = (const float*)d_in[2];
    const float* Wv = (const float*)d_in[3];
    const float* Wo = (const float*)d_in[4];
    float* out = (float*)d_out;

    cudaFuncSetAttribute(flash_kernel,
                         cudaFuncAttributeMaxDynamicSharedMemorySize, FLASH_SMEM);
    cudaFuncSetAttribute(outproj_kernel,
                         cudaFuncAttributeMaxDynamicSharedMemorySize, OP_SMEM);

    // Pack all weights into fp16 k-pair layout (tiny)
    packw_kernel<<<1024, 256>>>(Wq, Wk, Wv, Wo);

    // QKV projections: A = fp32 x (cvt), B = packed weights via cp.async
    qkv_kernel<<<dim3(RR / 128, 1, 3), 256>>>(x);

    // Split-KV causal flash attention (288 blocks = full wave at 2/SM)
    flash_kernel<<<NSLOT, 256, FLASH_SMEM>>>();

    // Merge partial softmax chunks -> packed fp16 O
    combine_kernel<<<RR * 32 / 256, 256>>>();

    // Output projection: one-shot smem, no mainloop barriers
    outproj_kernel<<<dim3(DD / 128, RR / 128), 256, OP_SMEM>>>(out);
}